// round 4
// baseline (speedup 1.0000x reference)
#include <cuda_runtime.h>
#include <math.h>
#include <stdint.h>

#define BB 512
#define NN 50
#define DD 768
#define D4 3072
#define FLAT (NN*DD)   // 38400

// ---------------- scratch (__device__ globals; no allocation allowed) ----------------
__device__ float    g_text[BB*FLAT];
__device__ float    g_vis [BB*FLAT];
__device__ float    g_ac  [BB*FLAT];
__device__ uint32_t s_shift32[BB*FLAT];            // tf32 LN output
__device__ float    s_xg[(size_t)BB*NN*D4];        // permuted gate pre-activations
__device__ uint32_t s_h32[BB*DD];                  // tf32 hidden state
__device__ float    s_c  [BB*DD];
__device__ uint32_t s_vm32[BB*DD];
__device__ uint32_t s_am32[BB*DD];
__device__ float    s_fc [BB*DD];
__device__ uint32_t s_Wih32p[D4*DD];               // tf32, gate-interleaved rows
__device__ uint32_t s_Whh32p[D4*DD];               // tf32, gate-interleaved rows
__device__ uint32_t s_vW032 [DD*DD];
__device__ uint32_t s_W1232 [DD*DD];
__device__ float    s_bias_p[D4];                  // permuted bih+bhh
__device__ float    s_vbsum[DD];
__device__ int      s_mask[BB];

__device__ __forceinline__ uint32_t f2tf32(float x){
    uint32_t r; asm("cvt.rna.tf32.f32 %0, %1;" : "=r"(r) : "f"(x)); return r;
}
__device__ __forceinline__ float fsig(float x){
    return __fdividef(1.f, 1.f + __expf(-x));
}
__device__ __forceinline__ float ftanh(float x){
    return __fdividef(2.f, 1.f + __expf(-2.f*x)) - 1.f;
}

// ---------------- prep: convert weights to tf32 (permuted), combine biases ----------
__global__ __launch_bounds__(256) void prep_kernel(
    const float* __restrict__ Wih, const float* __restrict__ Whh,
    const float* __restrict__ bih, const float* __restrict__ bhh,
    const float* __restrict__ vW,  const float* __restrict__ vb)
{
    int i = blockIdx.x*256 + threadIdx.x;
    if (i < D4*DD) {
        int p = i / DD, k = i - p*DD;
        int orig = (p & 3)*DD + (p >> 2);          // gate-interleave: p = 4*jj + gate
        s_Wih32p[i] = f2tf32(Wih[(size_t)orig*DD + k]);
        s_Whh32p[i] = f2tf32(Whh[(size_t)orig*DD + k]);
    }
    if (i < D4) {
        int orig = (i & 3)*DD + (i >> 2);
        s_bias_p[i] = bih[orig] + bhh[orig];
    }
    if (i < DD*DD) {
        s_vW032[i] = f2tf32(vW[i]);
        s_W1232[i] = f2tf32(vW[DD*DD + i] + vW[2*DD*DD + i]);
    }
    if (i < DD) s_vbsum[i] = vb[i] + vb[DD+i] + vb[2*DD+i];
}

// ---------------- EGCE ----------------
__global__ __launch_bounds__(384) void egce_kernel(
    const float* __restrict__ text, const int* __restrict__ vids,
    const int* __restrict__ aids, const float* __restrict__ vemb,
    const float* __restrict__ aemb, const float* __restrict__ w3)
{
    int b = blockIdx.x;
    int mode = blockIdx.y;     // 0=text, 1=visual(relu gather), 2=acoustic(gather)
    int tid = threadIdx.x;
    __shared__ float gap[DD];
    __shared__ float att[DD];
    __shared__ int ids[NN];
    if (tid < NN)
        ids[tid] = (mode==1) ? vids[b*NN+tid] : (mode==2 ? aids[b*NN+tid] : 0);
    __syncthreads();

    const float* src = (mode==0) ? (text + (size_t)b*FLAT) : (mode==1 ? vemb : aemb);

    auto fetch = [&](int k)->float {
        if (mode == 0) return src[k];
        int n = k / DD; int d = k - n*DD;
        float v = src[(size_t)ids[n]*DD + d];
        if (mode == 1) v = fmaxf(v, 0.f);
        return v;
    };

    for (int ch = tid; ch < DD; ch += 384) {
        float s = 0.f; int base = ch*NN;
        #pragma unroll 5
        for (int j = 0; j < NN; j++) s += fetch(base+j);
        gap[ch] = s * (1.f/NN);
    }
    __syncthreads();
    float w0 = w3[0], w1 = w3[1], w2 = w3[2];
    for (int ch = tid; ch < DD; ch += 384) {
        float a = w1*gap[ch];
        if (ch > 0)    a += w0*gap[ch-1];
        if (ch < DD-1) a += w2*gap[ch+1];
        att[ch] = 1.f/(1.f+expf(-a));
    }
    __syncthreads();
    float* out = ((mode==0) ? g_text : (mode==1 ? g_vis : g_ac)) + (size_t)b*FLAT;
    for (int k = tid; k < FLAT; k += 384)
        out[k] = fetch(k) * att[k/NN];
}

// ---------------- means over n, cosine sims, routing mask ----------------
__global__ __launch_bounds__(256) void means_cos_kernel()
{
    int b = blockIdx.x, tid = threadIdx.x;
    __shared__ float mt[DD], mv[DD], ma[DD];
    const float* pt = g_text + (size_t)b*FLAT;
    const float* pv = g_vis  + (size_t)b*FLAT;
    const float* pa = g_ac   + (size_t)b*FLAT;
    for (int d = tid; d < DD; d += 256) {
        float st=0.f, sv=0.f, sa=0.f;
        for (int n = 0; n < NN; n++) {
            st += pt[n*DD+d]; sv += pv[n*DD+d]; sa += pa[n*DD+d];
        }
        st *= (1.f/NN); sv *= (1.f/NN); sa *= (1.f/NN);
        mt[d]=st; mv[d]=sv; ma[d]=sa;
        s_vm32[b*DD+d] = f2tf32(sv);
        s_am32[b*DD+d] = f2tf32(sa);
    }
    __syncthreads();
    float p[6] = {0,0,0,0,0,0};  // tv, ta, va, tt, vv, aa
    for (int d = tid; d < DD; d += 256) {
        float t=mt[d], v=mv[d], a=ma[d];
        p[0]+=t*v; p[1]+=t*a; p[2]+=v*a; p[3]+=t*t; p[4]+=v*v; p[5]+=a*a;
    }
    __shared__ float red[256];
    __shared__ float res[6];
    for (int q = 0; q < 6; q++) {
        red[tid] = p[q]; __syncthreads();
        for (int s = 128; s > 0; s >>= 1) {
            if (tid < s) red[tid] += red[tid+s];
            __syncthreads();
        }
        if (tid == 0) res[q] = red[0];
        __syncthreads();
    }
    if (tid == 0) {
        float nt = fmaxf(sqrtf(res[3]), 1e-8f);
        float nv = fmaxf(sqrtf(res[4]), 1e-8f);
        float na = fmaxf(sqrtf(res[5]), 1e-8f);
        float rtv = res[0]/(nt*nv), rta = res[1]/(nt*na), rva = res[2]/(nv*na);
        float delta = (rtv + rta + rva) * (1.f/3.f);
        int mk;
        if (rtv > delta && rta > delta && rva > delta) mk = 0;       // f_concat
        else                                           mk = 2;       // f_cross (joint>delta impossible)
        s_mask[b] = mk;
    }
}

// ================= tf32 mma mainloop (shared by both GEMM kernels) =================
// Computes 128x128 tile: acc += A[128,K] @ B[128,K]^T, operands pre-converted tf32.
// Smem: fragment-major layout; A frags via lds.128, B frags via lds.64;
// fragments double-buffered against the mma issue stream.
__device__ __forceinline__ void mainloop_tf32(
    const uint32_t* __restrict__ Ab, const uint32_t* __restrict__ Bb, int K,
    uint32_t* Sh, float (&acc)[4][4][4])
{
    uint32_t* As = Sh;           // 4096 words (128m x 32k, fragment-major)
    uint32_t* Bs = Sh + 4096;    // 4096 words (128n x 32k, fragment-major)
    int tid  = threadIdx.x;
    int warp = tid >> 5, lane = tid & 31;
    int wm = (warp >> 2) * 64;
    int wn = (warp & 3) * 32;
    int miw0 = wm >> 4;          // 0 or 4
    int njw0 = wn >> 3;          // 0,4,8,12
    int lrow = tid >> 3;         // 0..31
    int lcol = (tid & 7) * 4;    // 0..28
    int kg_s = lcol >> 3;
    int regA2 = 2 * ((lcol >> 2) & 1);
    int regB  = (lcol >> 2) & 1;

    uint4 aR[4], bR[4];

    auto ldg = [&](int k0){
        #pragma unroll
        for (int p = 0; p < 4; p++) {
            aR[p] = *reinterpret_cast<const uint4*>(Ab + (size_t)(p*32+lrow)*K + k0 + lcol);
            bR[p] = *reinterpret_cast<const uint4*>(Bb + (size_t)(p*32+lrow)*K + k0 + lcol);
        }
    };
    auto sts = [&](){
        #pragma unroll
        for (int p = 0; p < 4; p++) {
            int row = p*32 + lrow;
            int baseA = ((kg_s*8 + (row>>4))*32 + (row&7)*4)*4 + ((row>>3)&1) + regA2;
            As[baseA+0]  = aR[p].x; As[baseA+4]  = aR[p].y;
            As[baseA+8]  = aR[p].z; As[baseA+12] = aR[p].w;
            int baseB = ((kg_s*16 + (row>>3))*32 + (row&7)*4)*2 + regB;
            Bs[baseB+0] = bR[p].x; Bs[baseB+2] = bR[p].y;
            Bs[baseB+4] = bR[p].z; Bs[baseB+6] = bR[p].w;
        }
    };

    uint32_t af[2][4][4];
    uint32_t bf_[2][4][2];
    auto ldfrag = [&](int kg, int buf){
        #pragma unroll
        for (int mi = 0; mi < 4; mi++) {
            uint4 v = *reinterpret_cast<const uint4*>(&As[((kg*8 + miw0 + mi)*32 + lane)*4]);
            af[buf][mi][0]=v.x; af[buf][mi][1]=v.y; af[buf][mi][2]=v.z; af[buf][mi][3]=v.w;
        }
        #pragma unroll
        for (int ni = 0; ni < 4; ni++) {
            uint2 v = *reinterpret_cast<const uint2*>(&Bs[((kg*16 + njw0 + ni)*32 + lane)*2]);
            bf_[buf][ni][0]=v.x; bf_[buf][ni][1]=v.y;
        }
    };
    auto domma = [&](int buf){
        #pragma unroll
        for (int mi = 0; mi < 4; mi++)
            #pragma unroll
            for (int ni = 0; ni < 4; ni++)
                asm volatile(
                  "mma.sync.aligned.m16n8k8.row.col.f32.tf32.tf32.f32 "
                  "{%0,%1,%2,%3}, {%4,%5,%6,%7}, {%8,%9}, {%0,%1,%2,%3};"
                  : "+f"(acc[mi][ni][0]), "+f"(acc[mi][ni][1]),
                    "+f"(acc[mi][ni][2]), "+f"(acc[mi][ni][3])
                  : "r"(af[buf][mi][0]), "r"(af[buf][mi][1]),
                    "r"(af[buf][mi][2]), "r"(af[buf][mi][3]),
                    "r"(bf_[buf][ni][0]), "r"(bf_[buf][ni][1]));
    };

    ldg(0); sts(); __syncthreads();
    for (int k0 = 32; k0 <= K; k0 += 32) {
        if (k0 < K) ldg(k0);
        ldfrag(0, 0);
        #pragma unroll
        for (int kg = 0; kg < 4; kg++) {
            if (kg < 3) ldfrag(kg+1, (kg+1)&1);
            domma(kg&1);
        }
        __syncthreads();
        if (k0 < K) { sts(); __syncthreads(); }
    }
}

// ---------------- generic GEMM: C[M,N] = A@B^T with epilogue options --------------
__global__ __launch_bounds__(256,1) void gemm_tf32_v2(
    const uint32_t* __restrict__ A, const uint32_t* __restrict__ Bm, float* __restrict__ C,
    int M, int Nn, int K,
    const float* __restrict__ bias, int accumulate, float out_scale)
{
    __shared__ __align__(16) uint32_t Sh[8192];
    float acc[4][4][4];
    #pragma unroll
    for (int i=0;i<4;i++) for (int j=0;j<4;j++) for (int r=0;r<4;r++) acc[i][j][r]=0.f;

    mainloop_tf32(A + (size_t)blockIdx.y*128*K, Bm + (size_t)blockIdx.x*128*K, K, Sh, acc);

    int tid = threadIdx.x;
    int warp = tid >> 5, lane = tid & 31;
    int wm = (warp >> 2) * 64, wn = (warp & 3) * 32;
    int g = lane >> 2, cq = lane & 3;
    int row0 = blockIdx.y*128 + wm;
    int col0 = blockIdx.x*128 + wn;
    #pragma unroll
    for (int mi = 0; mi < 4; mi++)
        #pragma unroll
        for (int ni = 0; ni < 4; ni++)
            #pragma unroll
            for (int r = 0; r < 4; r++) {
                int row = row0 + mi*16 + g + (r >> 1)*8;
                int n   = col0 + ni*8 + 2*cq + (r & 1);
                size_t idx = (size_t)row*Nn + n;
                float v = acc[mi][ni][r];
                if (accumulate) v += C[idx];
                if (bias)       v += bias[n];
                C[idx] = v * out_scale;
            }
}

// ---------------- recurrence GEMM with fused LSTM gate epilogue -------------------
// A = s_h32 [512,768] tf32, B = s_Whh32p [3072,768] (gate-interleaved rows).
// acc(b, p=4jj+gate) + xg(b,t,p) -> gates -> c,h update, out residual.
__global__ __launch_bounds__(256,1) void gemm_lstm_step(int t, float* __restrict__ out)
{
    __shared__ __align__(16) uint32_t Sh[8192];
    float acc[4][4][4];
    #pragma unroll
    for (int i=0;i<4;i++) for (int j=0;j<4;j++) for (int r=0;r<4;r++) acc[i][j][r]=0.f;

    mainloop_tf32(s_h32 + (size_t)blockIdx.y*128*DD,
                  s_Whh32p + (size_t)blockIdx.x*128*DD, DD, Sh, acc);

    float* ebuf = (float*)Sh;           // 64 rows x 128 cols, XOR-swizzled
    int tid = threadIdx.x;
    int warp = tid >> 5, lane = tid & 31;
    int wm = (warp >> 2) * 64, wn = (warp & 3) * 32;
    int g = lane >> 2, cq = lane & 3;
    int jj_l = tid & 31, rgrp = tid >> 5;   // rgrp = warp id (0..7)

    #pragma unroll
    for (int hf = 0; hf < 2; hf++) {
        __syncthreads();
        if ((wm >> 6) == hf) {
            #pragma unroll
            for (int mi = 0; mi < 4; mi++)
                #pragma unroll
                for (int ni = 0; ni < 4; ni++) {
                    int c0 = wn + ni*8 + 2*cq;
                    int r0 = mi*16 + g;
                    *reinterpret_cast<float2*>(&ebuf[r0*128 + (c0 ^ ((r0&7)<<2))]) =
                        make_float2(acc[mi][ni][0], acc[mi][ni][1]);
                    int r1 = r0 + 8;
                    *reinterpret_cast<float2*>(&ebuf[r1*128 + (c0 ^ ((r1&7)<<2))]) =
                        make_float2(acc[mi][ni][2], acc[mi][ni][3]);
                }
        }
        __syncthreads();
        #pragma unroll
        for (int q = 0; q < 8; q++) {
            int r = rgrp + 8*q;                       // r&7 == rgrp
            int b = blockIdx.y*128 + hf*64 + r;
            int jjg = blockIdx.x*32 + jj_l;
            float4 acq = *reinterpret_cast<const float4*>(
                &ebuf[r*128 + ((4*jj_l) ^ (rgrp<<2))]);
            float4 xq = *reinterpret_cast<const float4*>(
                &s_xg[((size_t)b*NN + t)*D4 + blockIdx.x*128 + 4*jj_l]);
            float gi = acq.x + xq.x, gf = acq.y + xq.y;
            float gg = acq.z + xq.z, go = acq.w + xq.w;
            int ci = b*DD + jjg;
            float c = s_c[ci];
            float cn = fsig(gf)*c + fsig(gi)*ftanh(gg);
            s_c[ci] = cn;
            float hn = fsig(go)*ftanh(cn);
            s_h32[ci] = f2tf32(hn);
            size_t oo = ((size_t)b*NN + t)*DD + jjg;
            out[oo] = hn + g_text[oo];
        }
    }
}

// ---------------- LSTM step 0 (h=c=0): gates directly from xg ----------------
__global__ __launch_bounds__(256) void lstm_step0_kernel(float* __restrict__ out)
{
    int id = blockIdx.x*256 + threadIdx.x;   // < B*D
    int b = id / DD, jj = id - b*DD;
    float4 xq = *reinterpret_cast<const float4*>(&s_xg[((size_t)b*NN)*D4 + 4*jj]);
    float cn = fsig(xq.x) * ftanh(xq.z);
    s_c[id] = cn;
    float hn = fsig(xq.w) * ftanh(cn);
    s_h32[id] = f2tf32(hn);
    size_t oo = ((size_t)b*NN)*DD + jj;
    out[oo] = hn + g_text[oo];
}

// ---------------- fusion select + residual + LayerNorm -> shift (tf32) -------------
__global__ __launch_bounds__(256) void fusion_ln_kernel(
    const float* __restrict__ cW, const float* __restrict__ cb,
    const float* __restrict__ hW, const float* __restrict__ hb,
    const float* __restrict__ ln_g, const float* __restrict__ ln_b)
{
    int bn = blockIdx.x;           // b*50 + n
    int b = bn / NN;
    int tid = threadIdx.x;
    __shared__ float buf[DD];
    __shared__ float cat[3*DD];
    __shared__ float r1[256], r2[256];
    const float* txt = g_text + (size_t)bn*DD;
    int mk = s_mask[b];
    if (mk == 2) {
        const float* fc = s_fc + (size_t)b*DD;
        for (int d = tid; d < DD; d += 256) buf[d] = fc[d] + txt[d];
    } else {
        const float* pv = g_vis + (size_t)bn*DD;
        const float* pa = g_ac  + (size_t)bn*DD;
        for (int k = tid; k < DD; k += 256) {
            cat[k] = txt[k]; cat[DD+k] = pv[k]; cat[2*DD+k] = pa[k];
        }
        __syncthreads();
        const float* W  = cW;
        const float* bv = cb;
        for (int d = tid; d < DD; d += 256) {
            const float* wr = W + (size_t)d*3*DD;
            float s = bv[d];
            for (int k = 0; k < 3*DD; k++) s += cat[k]*wr[k];
            buf[d] = s + txt[d];
        }
    }
    __syncthreads();
    float ps = 0.f;
    for (int d = tid; d < DD; d += 256) ps += buf[d];
    r1[tid] = ps; __syncthreads();
    for (int s = 128; s > 0; s >>= 1) { if (tid < s) r1[tid] += r1[tid+s]; __syncthreads(); }
    float mean = r1[0] * (1.f/DD);
    float pq = 0.f;
    for (int d = tid; d < DD; d += 256) { float x = buf[d]-mean; pq += x*x; }
    r2[tid] = pq; __syncthreads();
    for (int s = 128; s > 0; s >>= 1) { if (tid < s) r2[tid] += r2[tid+s]; __syncthreads(); }
    float rstd = rsqrtf(r2[0]*(1.f/DD) + 1e-5f);
    uint32_t* outp = s_shift32 + (size_t)bn*DD;
    for (int d = tid; d < DD; d += 256)
        outp[d] = f2tf32((buf[d]-mean)*rstd*ln_g[d] + ln_b[d]);
}

// ---------------- launch ----------------
extern "C" void kernel_launch(void* const* d_in, const int* in_sizes, int n_in,
                              void* d_out, int out_size)
{
    const float* text = (const float*)d_in[0];
    const int*   vids = (const int*)  d_in[1];
    const int*   aids = (const int*)  d_in[2];
    const float* vemb = (const float*)d_in[3];
    const float* aemb = (const float*)d_in[4];
    const float* w3   = (const float*)d_in[5];
    const float* Wih  = (const float*)d_in[6];
    const float* Whh  = (const float*)d_in[7];
    const float* bih  = (const float*)d_in[8];
    const float* bhh  = (const float*)d_in[9];
    const float* lng  = (const float*)d_in[10];
    const float* lnb  = (const float*)d_in[11];
    const float* cW   = (const float*)d_in[12];
    const float* cb   = (const float*)d_in[13];
    const float* hW   = (const float*)d_in[14];
    const float* hb   = (const float*)d_in[15];
    const float* vW   = (const float*)d_in[20];   // ca_vW [3,768,768]
    const float* vb   = (const float*)d_in[21];   // ca_vb [3,768]
    float* out = (float*)d_out;

    uint32_t *p_vm32, *p_am32, *p_shift32, *p_vW032, *p_W1232, *p_Wih32p;
    float *p_fc, *p_vbsum, *p_xg, *p_bias_p;
    cudaGetSymbolAddress((void**)&p_vm32, s_vm32);
    cudaGetSymbolAddress((void**)&p_am32, s_am32);
    cudaGetSymbolAddress((void**)&p_shift32, s_shift32);
    cudaGetSymbolAddress((void**)&p_vW032, s_vW032);
    cudaGetSymbolAddress((void**)&p_W1232, s_W1232);
    cudaGetSymbolAddress((void**)&p_Wih32p, s_Wih32p);
    cudaGetSymbolAddress((void**)&p_fc, s_fc);
    cudaGetSymbolAddress((void**)&p_vbsum, s_vbsum);
    cudaGetSymbolAddress((void**)&p_xg, s_xg);
    cudaGetSymbolAddress((void**)&p_bias_p, s_bias_p);

    prep_kernel<<<(D4*DD + 255)/256, 256>>>(Wih, Whh, bih, bhh, vW, vb);
    egce_kernel<<<dim3(BB, 3), 384>>>(text, vids, aids, vemb, aemb, w3);
    means_cos_kernel<<<BB, 256>>>();

    // f_cross: fc = (vm@vW0^T + am@(vW1+vW2)^T + vbsum) * (50/3)
    gemm_tf32_v2<<<dim3(DD/128, BB/128), 256>>>(p_vm32, p_vW032, p_fc,
                                                BB, DD, DD, nullptr, 0, 1.f);
    gemm_tf32_v2<<<dim3(DD/128, BB/128), 256>>>(p_am32, p_W1232, p_fc,
                                                BB, DD, DD, p_vbsum, 1, 50.f/3.f);

    fusion_ln_kernel<<<BB*NN, 256>>>(cW, cb, hW, hb, lng, lnb);

    // xg = shift @ Wih_perm^T + bias_perm   [25600, 3072] (gate-interleaved cols)
    gemm_tf32_v2<<<dim3(D4/128, (BB*NN)/128), 256>>>(p_shift32, p_Wih32p, p_xg,
                                                     BB*NN, D4, DD, p_bias_p, 0, 1.f);

    // LSTM: t=0 directly from xg; t=1..49 GEMM with fused gate epilogue
    lstm_step0_kernel<<<(BB*DD)/256, 256>>>(out);
    for (int t = 1; t < NN; t++)
        gemm_lstm_step<<<dim3(D4/128, BB/128), 256>>>(t, out);
}

// round 7
// speedup vs baseline: 1.3070x; 1.3070x over previous
#include <cuda_runtime.h>
#include <math.h>
#include <stdint.h>

#define BB 512
#define NN 50
#define DD 768
#define D4 3072
#define FLAT (NN*DD)   // 38400

#define STAGE_WORDS 9216            // (128*36)*2 per stage (A + B)
#define SMEM_BYTES (3*STAGE_WORDS*4)  // 110592

// ---------------- scratch (__device__ globals; no allocation allowed) ----------------
__device__ float    g_text[BB*FLAT];
__device__ float    g_vis [BB*FLAT];
__device__ float    g_ac  [BB*FLAT];
__device__ uint32_t s_shift32[BB*FLAT];            // tf32 LN output
__device__ float    s_xg[(size_t)BB*NN*D4];        // permuted gate pre-activations
__device__ uint32_t s_h32[BB*DD];                  // tf32 hidden state
__device__ float    s_c  [BB*DD];
__device__ uint32_t s_vmam32[BB*2*DD];             // [b][vm|am] tf32
__device__ float    s_fc [BB*DD];
__device__ uint32_t s_Wih32p[D4*DD];               // tf32, gate-interleaved rows
__device__ uint32_t s_Whh32p[D4*DD];               // tf32, gate-interleaved rows
__device__ uint32_t s_vWc32 [DD*2*DD];             // [n][vW0|vW1+vW2] tf32
__device__ float    s_bias_p[D4];                  // permuted bih+bhh
__device__ float    s_vbsum[DD];
__device__ int      s_mask[BB];

__device__ __forceinline__ uint32_t f2tf32(float x){
    uint32_t r; asm("cvt.rna.tf32.f32 %0, %1;" : "=r"(r) : "f"(x)); return r;
}
__device__ __forceinline__ float fsig(float x){
    return __fdividef(1.f, 1.f + __expf(-x));
}
__device__ __forceinline__ float ftanh(float x){
    return __fdividef(2.f, 1.f + __expf(-2.f*x)) - 1.f;
}

// ---------------- prep: convert weights to tf32 (permuted), combine biases ----------
__global__ __launch_bounds__(256) void prep_kernel(
    const float* __restrict__ Wih, const float* __restrict__ Whh,
    const float* __restrict__ bih, const float* __restrict__ bhh,
    const float* __restrict__ vW,  const float* __restrict__ vb)
{
    int i = blockIdx.x*256 + threadIdx.x;
    if (i < D4*DD) {
        int p = i / DD, k = i - p*DD;
        int orig = (p & 3)*DD + (p >> 2);          // gate-interleave: p = 4*jj + gate
        s_Wih32p[i] = f2tf32(Wih[(size_t)orig*DD + k]);
        s_Whh32p[i] = f2tf32(Whh[(size_t)orig*DD + k]);
    }
    if (i < D4) {
        int orig = (i & 3)*DD + (i >> 2);
        s_bias_p[i] = bih[orig] + bhh[orig];
    }
    if (i < DD*DD) {
        int n = i / DD, k = i - n*DD;
        s_vWc32[(size_t)n*2*DD + k]      = f2tf32(vW[i]);
        s_vWc32[(size_t)n*2*DD + DD + k] = f2tf32(vW[DD*DD + i] + vW[2*DD*DD + i]);
    }
    if (i < DD) s_vbsum[i] = vb[i] + vb[DD+i] + vb[2*DD+i];
}

// ---------------- EGCE ----------------
__global__ __launch_bounds__(384) void egce_kernel(
    const float* __restrict__ text, const int* __restrict__ vids,
    const int* __restrict__ aids, const float* __restrict__ vemb,
    const float* __restrict__ aemb, const float* __restrict__ w3)
{
    int b = blockIdx.x;
    int mode = blockIdx.y;     // 0=text, 1=visual(relu gather), 2=acoustic(gather)
    int tid = threadIdx.x;
    __shared__ float gap[DD];
    __shared__ float att[DD];
    __shared__ int ids[NN];
    if (tid < NN)
        ids[tid] = (mode==1) ? vids[b*NN+tid] : (mode==2 ? aids[b*NN+tid] : 0);
    __syncthreads();

    const float* src = (mode==0) ? (text + (size_t)b*FLAT) : (mode==1 ? vemb : aemb);

    auto fetch = [&](int k)->float {
        if (mode == 0) return src[k];
        int n = k / DD; int d = k - n*DD;
        float v = src[(size_t)ids[n]*DD + d];
        if (mode == 1) v = fmaxf(v, 0.f);
        return v;
    };

    for (int ch = tid; ch < DD; ch += 384) {
        float s = 0.f; int base = ch*NN;
        #pragma unroll 5
        for (int j = 0; j < NN; j++) s += fetch(base+j);
        gap[ch] = s * (1.f/NN);
    }
    __syncthreads();
    float w0 = w3[0], w1 = w3[1], w2 = w3[2];
    for (int ch = tid; ch < DD; ch += 384) {
        float a = w1*gap[ch];
        if (ch > 0)    a += w0*gap[ch-1];
        if (ch < DD-1) a += w2*gap[ch+1];
        att[ch] = 1.f/(1.f+expf(-a));
    }
    __syncthreads();
    float* out = ((mode==0) ? g_text : (mode==1 ? g_vis : g_ac)) + (size_t)b*FLAT;
    for (int k = tid; k < FLAT; k += 384)
        out[k] = fetch(k) * att[k/NN];
}

// ---------------- means over n, cosine sims, routing mask ----------------
__global__ __launch_bounds__(256) void means_cos_kernel()
{
    int b = blockIdx.x, tid = threadIdx.x;
    __shared__ float mt[DD], mv[DD], ma[DD];
    const float* pt = g_text + (size_t)b*FLAT;
    const float* pv = g_vis  + (size_t)b*FLAT;
    const float* pa = g_ac   + (size_t)b*FLAT;
    for (int d = tid; d < DD; d += 256) {
        float st=0.f, sv=0.f, sa=0.f;
        for (int n = 0; n < NN; n++) {
            st += pt[n*DD+d]; sv += pv[n*DD+d]; sa += pa[n*DD+d];
        }
        st *= (1.f/NN); sv *= (1.f/NN); sa *= (1.f/NN);
        mt[d]=st; mv[d]=sv; ma[d]=sa;
        s_vmam32[(size_t)b*2*DD + d]      = f2tf32(sv);
        s_vmam32[(size_t)b*2*DD + DD + d] = f2tf32(sa);
    }
    __syncthreads();
    float p[6] = {0,0,0,0,0,0};  // tv, ta, va, tt, vv, aa
    for (int d = tid; d < DD; d += 256) {
        float t=mt[d], v=mv[d], a=ma[d];
        p[0]+=t*v; p[1]+=t*a; p[2]+=v*a; p[3]+=t*t; p[4]+=v*v; p[5]+=a*a;
    }
    __shared__ float red[256];
    __shared__ float res[6];
    for (int q = 0; q < 6; q++) {
        red[tid] = p[q]; __syncthreads();
        for (int s = 128; s > 0; s >>= 1) {
            if (tid < s) red[tid] += red[tid+s];
            __syncthreads();
        }
        if (tid == 0) res[q] = red[0];
        __syncthreads();
    }
    if (tid == 0) {
        float nt = fmaxf(sqrtf(res[3]), 1e-8f);
        float nv = fmaxf(sqrtf(res[4]), 1e-8f);
        float na = fmaxf(sqrtf(res[5]), 1e-8f);
        float rtv = res[0]/(nt*nv), rta = res[1]/(nt*na), rva = res[2]/(nv*na);
        float delta = (rtv + rta + rva) * (1.f/3.f);
        int mk;
        if (rtv > delta && rta > delta && rva > delta) mk = 0;       // f_concat
        else                                           mk = 2;       // f_cross
        s_mask[b] = mk;
    }
}

// ================= tf32 mma mainloop: cp.async 3-stage + padded smem ================
// 128x128 tile: acc += A[128,K] @ B[128,K]^T; operands pre-converted tf32 in gmem.
// Smem per stage: A[128][36] + B[128][36] (padding=4 words -> conflict-free LDS).
__device__ __forceinline__ void mainloop_tf32(
    const uint32_t* __restrict__ Ab, const uint32_t* __restrict__ Bb, int K,
    uint32_t* Sh, float (&acc)[4][4][4])
{
    int tid  = threadIdx.x;
    int warp = tid >> 5, lane = tid & 31;
    int wm = (warp >> 2) * 64;
    int wn = (warp & 3) * 32;
    int g  = lane >> 2;
    int cq = lane & 3;
    int lrow = tid >> 3;            // 0..31
    int lcol = (tid & 7) * 4;       // 0,4,...,28
    int ntiles = K >> 5;

    auto issue_stage = [&](int kt, int s){
        uint32_t* As = Sh + s*STAGE_WORDS;
        uint32_t* Bs = As + 4608;
        const uint32_t* ga = Ab + (size_t)lrow*K + kt*32 + lcol;
        const uint32_t* gb = Bb + (size_t)lrow*K + kt*32 + lcol;
        uint32_t da = (uint32_t)__cvta_generic_to_shared(&As[lrow*36 + lcol]);
        uint32_t db = (uint32_t)__cvta_generic_to_shared(&Bs[lrow*36 + lcol]);
        #pragma unroll
        for (int p = 0; p < 4; p++) {
            asm volatile("cp.async.cg.shared.global [%0], [%1], 16;"
                         :: "r"(da + p*32*36*4), "l"(ga + (size_t)p*32*K) : "memory");
            asm volatile("cp.async.cg.shared.global [%0], [%1], 16;"
                         :: "r"(db + p*32*36*4), "l"(gb + (size_t)p*32*K) : "memory");
        }
        asm volatile("cp.async.commit_group;" ::: "memory");
    };

    issue_stage(0, 0);
    issue_stage(1, 1);

    for (int kt = 0; kt < ntiles; kt++) {
        if (kt + 1 < ntiles) asm volatile("cp.async.wait_group 1;" ::: "memory");
        else                 asm volatile("cp.async.wait_group 0;" ::: "memory");
        __syncthreads();
        if (kt + 2 < ntiles) issue_stage(kt + 2, (kt + 2) % 3);

        const uint32_t* As = Sh + (kt % 3)*STAGE_WORDS;
        const uint32_t* Bs = As + 4608;
        #pragma unroll
        for (int kk = 0; kk < 32; kk += 8) {
            uint32_t af[4][4], bf_[4][2];
            #pragma unroll
            for (int mi = 0; mi < 4; mi++) {
                int r = wm + mi*16 + g;
                af[mi][0] = As[r*36 + kk+cq];
                af[mi][1] = As[(r+8)*36 + kk+cq];
                af[mi][2] = As[r*36 + kk+cq+4];
                af[mi][3] = As[(r+8)*36 + kk+cq+4];
            }
            #pragma unroll
            for (int ni = 0; ni < 4; ni++) {
                int cb2 = wn + ni*8 + g;
                bf_[ni][0] = Bs[cb2*36 + kk+cq];
                bf_[ni][1] = Bs[cb2*36 + kk+cq+4];
            }
            #pragma unroll
            for (int mi = 0; mi < 4; mi++)
                #pragma unroll
                for (int ni = 0; ni < 4; ni++)
                    asm volatile(
                      "mma.sync.aligned.m16n8k8.row.col.f32.tf32.tf32.f32 "
                      "{%0,%1,%2,%3}, {%4,%5,%6,%7}, {%8,%9}, {%0,%1,%2,%3};"
                      : "+f"(acc[mi][ni][0]), "+f"(acc[mi][ni][1]),
                        "+f"(acc[mi][ni][2]), "+f"(acc[mi][ni][3])
                      : "r"(af[mi][0]), "r"(af[mi][1]), "r"(af[mi][2]), "r"(af[mi][3]),
                        "r"(bf_[ni][0]), "r"(bf_[ni][1]));
        }
    }
}

// ---------------- generic GEMM: C[M,N] = A@B^T with epilogue options --------------
__global__ __launch_bounds__(256,1) void gemm_tf32_v2(
    const uint32_t* __restrict__ A, const uint32_t* __restrict__ Bm, float* __restrict__ C,
    int M, int Nn, int K,
    const float* __restrict__ bias, float out_scale)
{
    extern __shared__ __align__(16) uint32_t Sh[];
    float acc[4][4][4];
    #pragma unroll
    for (int i=0;i<4;i++) for (int j=0;j<4;j++) for (int r=0;r<4;r++) acc[i][j][r]=0.f;

    mainloop_tf32(A + (size_t)blockIdx.y*128*K, Bm + (size_t)blockIdx.x*128*K, K, Sh, acc);

    int tid = threadIdx.x;
    int warp = tid >> 5, lane = tid & 31;
    int wm = (warp >> 2) * 64, wn = (warp & 3) * 32;
    int g = lane >> 2, cq = lane & 3;
    int row0 = blockIdx.y*128 + wm;
    int col0 = blockIdx.x*128 + wn;
    #pragma unroll
    for (int mi = 0; mi < 4; mi++)
        #pragma unroll
        for (int ni = 0; ni < 4; ni++)
            #pragma unroll
            for (int r = 0; r < 4; r++) {
                int row = row0 + mi*16 + g + (r >> 1)*8;
                int n   = col0 + ni*8 + 2*cq + (r & 1);
                float v = acc[mi][ni][r];
                if (bias) v += bias[n];
                C[(size_t)row*Nn + n] = v * out_scale;
            }
}

// ---------------- recurrence GEMM with fused LSTM gate epilogue -------------------
__global__ __launch_bounds__(256,1) void gemm_lstm_step(int t, float* __restrict__ out)
{
    extern __shared__ __align__(16) uint32_t Sh[];
    float acc[4][4][4];
    #pragma unroll
    for (int i=0;i<4;i++) for (int j=0;j<4;j++) for (int r=0;r<4;r++) acc[i][j][r]=0.f;

    mainloop_tf32(s_h32 + (size_t)blockIdx.y*128*DD,
                  s_Whh32p + (size_t)blockIdx.x*128*DD, DD, Sh, acc);

    float* ebuf = (float*)Sh;           // 64 rows x 128 cols, XOR-swizzled
    int tid = threadIdx.x;
    int warp = tid >> 5, lane = tid & 31;
    int wm = (warp >> 2) * 64, wn = (warp & 3) * 32;
    int g = lane >> 2, cq = lane & 3;
    int jj_l = tid & 31, rgrp = tid >> 5;   // rgrp = warp id (0..7)

    #pragma unroll
    for (int hf = 0; hf < 2; hf++) {
        __syncthreads();
        if ((wm >> 6) == hf) {
            #pragma unroll
            for (int mi = 0; mi < 4; mi++)
                #pragma unroll
                for (int ni = 0; ni < 4; ni++) {
                    int c0 = wn + ni*8 + 2*cq;
                    int r0 = mi*16 + g;
                    *reinterpret_cast<float2*>(&ebuf[r0*128 + (c0 ^ ((r0&7)<<2))]) =
                        make_float2(acc[mi][ni][0], acc[mi][ni][1]);
                    int r1 = r0 + 8;
                    *reinterpret_cast<float2*>(&ebuf[r1*128 + (c0 ^ ((r1&7)<<2))]) =
                        make_float2(acc[mi][ni][2], acc[mi][ni][3]);
                }
        }
        __syncthreads();
        #pragma unroll
        for (int q = 0; q < 8; q++) {
            int r = rgrp + 8*q;                       // r&7 == rgrp
            int b = blockIdx.y*128 + hf*64 + r;
            int jjg = blockIdx.x*32 + jj_l;
            float4 acq = *reinterpret_cast<const float4*>(
                &ebuf[r*128 + ((4*jj_l) ^ (rgrp<<2))]);
            float4 xq = *reinterpret_cast<const float4*>(
                &s_xg[((size_t)b*NN + t)*D4 + blockIdx.x*128 + 4*jj_l]);
            float gi = acq.x + xq.x, gf = acq.y + xq.y;
            float gg = acq.z + xq.z, go = acq.w + xq.w;
            int ci = b*DD + jjg;
            float c = s_c[ci];
            float cn = fsig(gf)*c + fsig(gi)*ftanh(gg);
            s_c[ci] = cn;
            float hn = fsig(go)*ftanh(cn);
            s_h32[ci] = f2tf32(hn);
            size_t oo = ((size_t)b*NN + t)*DD + jjg;
            out[oo] = hn + g_text[oo];
        }
    }
}

// ---------------- LSTM step 0 (h=c=0): gates directly from xg ----------------
__global__ __launch_bounds__(256) void lstm_step0_kernel(float* __restrict__ out)
{
    int id = blockIdx.x*256 + threadIdx.x;   // < B*D
    int b = id / DD, jj = id - b*DD;
    float4 xq = *reinterpret_cast<const float4*>(&s_xg[((size_t)b*NN)*D4 + 4*jj]);
    float cn = fsig(xq.x) * ftanh(xq.z);
    s_c[id] = cn;
    float hn = fsig(xq.w) * ftanh(cn);
    s_h32[id] = f2tf32(hn);
    size_t oo = ((size_t)b*NN)*DD + jj;
    out[oo] = hn + g_text[oo];
}

// ---------------- fusion select + residual + LayerNorm -> shift (tf32) -------------
__global__ __launch_bounds__(256) void fusion_ln_kernel(
    const float* __restrict__ cW, const float* __restrict__ cb,
    const float* __restrict__ hW, const float* __restrict__ hb,
    const float* __restrict__ ln_g, const float* __restrict__ ln_b)
{
    int bn = blockIdx.x;           // b*50 + n
    int b = bn / NN;
    int tid = threadIdx.x;
    __shared__ float buf[DD];
    __shared__ float cat[3*DD];
    __shared__ float r1[256], r2[256];
    const float* txt = g_text + (size_t)bn*DD;
    int mk = s_mask[b];
    if (mk == 2) {
        const float* fc = s_fc + (size_t)b*DD;
        for (int d = tid; d < DD; d += 256) buf[d] = fc[d] + txt[d];
    } else {
        const float* pv = g_vis + (size_t)bn*DD;
        const float* pa = g_ac  + (size_t)bn*DD;
        for (int k = tid; k < DD; k += 256) {
            cat[k] = txt[k]; cat[DD+k] = pv[k]; cat[2*DD+k] = pa[k];
        }
        __syncthreads();
        for (int d = tid; d < DD; d += 256) {
            const float* wr = cW + (size_t)d*3*DD;
            float s = cb[d];
            for (int k = 0; k < 3*DD; k++) s += cat[k]*wr[k];
            buf[d] = s + txt[d];
        }
    }
    __syncthreads();
    float ps = 0.f;
    for (int d = tid; d < DD; d += 256) ps += buf[d];
    r1[tid] = ps; __syncthreads();
    for (int s = 128; s > 0; s >>= 1) { if (tid < s) r1[tid] += r1[tid+s]; __syncthreads(); }
    float mean = r1[0] * (1.f/DD);
    float pq = 0.f;
    for (int d = tid; d < DD; d += 256) { float x = buf[d]-mean; pq += x*x; }
    r2[tid] = pq; __syncthreads();
    for (int s = 128; s > 0; s >>= 1) { if (tid < s) r2[tid] += r2[tid+s]; __syncthreads(); }
    float rstd = rsqrtf(r2[0]*(1.f/DD) + 1e-5f);
    uint32_t* outp = s_shift32 + (size_t)bn*DD;
    for (int d = tid; d < DD; d += 256)
        outp[d] = f2tf32((buf[d]-mean)*rstd*ln_g[d] + ln_b[d]);
}

// ---------------- launch ----------------
extern "C" void kernel_launch(void* const* d_in, const int* in_sizes, int n_in,
                              void* d_out, int out_size)
{
    const float* text = (const float*)d_in[0];
    const int*   vids = (const int*)  d_in[1];
    const int*   aids = (const int*)  d_in[2];
    const float* vemb = (const float*)d_in[3];
    const float* aemb = (const float*)d_in[4];
    const float* w3   = (const float*)d_in[5];
    const float* Wih  = (const float*)d_in[6];
    const float* Whh  = (const float*)d_in[7];
    const float* bih  = (const float*)d_in[8];
    const float* bhh  = (const float*)d_in[9];
    const float* lng  = (const float*)d_in[10];
    const float* lnb  = (const float*)d_in[11];
    const float* cW   = (const float*)d_in[12];
    const float* cb   = (const float*)d_in[13];
    const float* hW   = (const float*)d_in[14];
    const float* hb   = (const float*)d_in[15];
    const float* vW   = (const float*)d_in[20];   // ca_vW [3,768,768]
    const float* vb   = (const float*)d_in[21];   // ca_vb [3,768]
    float* out = (float*)d_out;

    cudaFuncSetAttribute(gemm_tf32_v2,
        cudaFuncAttributeMaxDynamicSharedMemorySize, SMEM_BYTES);
    cudaFuncSetAttribute(gemm_lstm_step,
        cudaFuncAttributeMaxDynamicSharedMemorySize, SMEM_BYTES);

    uint32_t *p_vmam32, *p_shift32, *p_vWc32, *p_Wih32p;
    float *p_fc, *p_vbsum, *p_xg, *p_bias_p;
    cudaGetSymbolAddress((void**)&p_vmam32, s_vmam32);
    cudaGetSymbolAddress((void**)&p_shift32, s_shift32);
    cudaGetSymbolAddress((void**)&p_vWc32, s_vWc32);
    cudaGetSymbolAddress((void**)&p_Wih32p, s_Wih32p);
    cudaGetSymbolAddress((void**)&p_fc, s_fc);
    cudaGetSymbolAddress((void**)&p_vbsum, s_vbsum);
    cudaGetSymbolAddress((void**)&p_xg, s_xg);
    cudaGetSymbolAddress((void**)&p_bias_p, s_bias_p);

    prep_kernel<<<(D4*DD + 255)/256, 256>>>(Wih, Whh, bih, bhh, vW, vb);
    egce_kernel<<<dim3(BB, 3), 384>>>(text, vids, aids, vemb, aemb, w3);
    means_cos_kernel<<<BB, 256>>>();

    // f_cross (single GEMM, K=1536): fc = ([vm|am] @ [vW0|W12]^T + vbsum) * (50/3)
    gemm_tf32_v2<<<dim3(DD/128, BB/128), 256, SMEM_BYTES>>>(
        p_vmam32, p_vWc32, p_fc, BB, DD, 2*DD, p_vbsum, 50.f/3.f);

    fusion_ln_kernel<<<BB*NN, 256>>>(cW, cb, hW, hb, lng, lnb);

    // xg = shift @ Wih_perm^T + bias_perm   [25600, 3072] (gate-interleaved cols)
    gemm_tf32_v2<<<dim3(D4/128, (BB*NN)/128), 256, SMEM_BYTES>>>(
        p_shift32, p_Wih32p, p_xg, BB*NN, D4, DD, p_bias_p, 1.f);

    // LSTM: t=0 directly from xg; t=1..49 GEMM with fused gate epilogue
    lstm_step0_kernel<<<(BB*DD)/256, 256>>>(out);
    for (int t = 1; t < NN; t++)
        gemm_lstm_step<<<dim3(D4/128, BB/128), 256, SMEM_BYTES>>>(t, out);
}

// round 9
// speedup vs baseline: 1.3816x; 1.0571x over previous
#include <cuda_runtime.h>
#include <math.h>
#include <stdint.h>

#define BB 512
#define NN 50
#define DD 768
#define D4 3072
#define FLAT (NN*DD)   // 38400

// ---------------- scratch (__device__ globals; no allocation allowed) ----------------
__device__ float    g_text[BB*FLAT];
__device__ float    g_vis [BB*FLAT];
__device__ float    g_ac  [BB*FLAT];
__device__ uint32_t s_shift32[BB*FLAT];            // tf32 LN output
__device__ float    s_xg[(size_t)BB*NN*D4];        // permuted gate pre-activations
__device__ uint32_t s_h32[BB*DD];                  // tf32 hidden state
__device__ float    s_c  [BB*DD];
__device__ uint32_t s_vmam32[BB*2*DD];             // [b][vm|am] tf32
__device__ float    s_fc [BB*DD];
__device__ uint32_t s_Wih32p[D4*DD];               // tf32, gate-interleaved rows
__device__ uint32_t s_Whh32p[D4*DD];               // tf32, gate-interleaved rows
__device__ uint32_t s_vWc32 [DD*2*DD];             // [n][vW0|vW1+vW2] tf32
__device__ float    s_bias_p[D4];                  // permuted bih+bhh
__device__ float    s_vbsum[DD];
__device__ int      s_mask[BB];

__device__ __forceinline__ uint32_t f2tf32(float x){
    uint32_t r; asm("cvt.rna.tf32.f32 %0, %1;" : "=r"(r) : "f"(x)); return r;
}
__device__ __forceinline__ float fsig(float x){
    return __fdividef(1.f, 1.f + __expf(-x));
}
__device__ __forceinline__ float ftanh(float x){
    return __fdividef(2.f, 1.f + __expf(-2.f*x)) - 1.f;
}
__device__ __forceinline__ uint32_t smem_u32(const void* p){
    uint32_t a;
    asm("{ .reg .u64 t; cvta.to.shared.u64 t, %1; cvt.u32.u64 %0, t; }"
        : "=r"(a) : "l"(p));
    return a;
}

// ---------------- prep: convert weights to tf32 (permuted), combine biases ----------
__global__ __launch_bounds__(256) void prep_kernel(
    const float* __restrict__ Wih, const float* __restrict__ Whh,
    const float* __restrict__ bih, const float* __restrict__ bhh,
    const float* __restrict__ vW,  const float* __restrict__ vb)
{
    int i = blockIdx.x*256 + threadIdx.x;
    if (i < D4*DD) {
        int p = i / DD, k = i - p*DD;
        int orig = (p & 3)*DD + (p >> 2);          // gate-interleave: p = 4*jj + gate
        s_Wih32p[i] = f2tf32(Wih[(size_t)orig*DD + k]);
        s_Whh32p[i] = f2tf32(Whh[(size_t)orig*DD + k]);
    }
    if (i < D4) {
        int orig = (i & 3)*DD + (i >> 2);
        s_bias_p[i] = bih[orig] + bhh[orig];
    }
    if (i < DD*DD) {
        int n = i / DD, k = i - n*DD;
        s_vWc32[(size_t)n*2*DD + k]      = f2tf32(vW[i]);
        s_vWc32[(size_t)n*2*DD + DD + k] = f2tf32(vW[DD*DD + i] + vW[2*DD*DD + i]);
    }
    if (i < DD) s_vbsum[i] = vb[i] + vb[DD+i] + vb[2*DD+i];
}

// ---------------- EGCE ----------------
__global__ __launch_bounds__(384) void egce_kernel(
    const float* __restrict__ text, const int* __restrict__ vids,
    const int* __restrict__ aids, const float* __restrict__ vemb,
    const float* __restrict__ aemb, const float* __restrict__ w3)
{
    int b = blockIdx.x;
    int mode = blockIdx.y;     // 0=text, 1=visual(relu gather), 2=acoustic(gather)
    int tid = threadIdx.x;
    __shared__ float gap[DD];
    __shared__ float att[DD];
    __shared__ int ids[NN];
    if (tid < NN)
        ids[tid] = (mode==1) ? vids[b*NN+tid] : (mode==2 ? aids[b*NN+tid] : 0);
    __syncthreads();

    const float* src = (mode==0) ? (text + (size_t)b*FLAT) : (mode==1 ? vemb : aemb);

    auto fetch = [&](int k)->float {
        if (mode == 0) return src[k];
        int n = k / DD; int d = k - n*DD;
        float v = src[(size_t)ids[n]*DD + d];
        if (mode == 1) v = fmaxf(v, 0.f);
        return v;
    };

    for (int ch = tid; ch < DD; ch += 384) {
        float s = 0.f; int base = ch*NN;
        #pragma unroll 5
        for (int j = 0; j < NN; j++) s += fetch(base+j);
        gap[ch] = s * (1.f/NN);
    }
    __syncthreads();
    float w0 = w3[0], w1 = w3[1], w2 = w3[2];
    for (int ch = tid; ch < DD; ch += 384) {
        float a = w1*gap[ch];
        if (ch > 0)    a += w0*gap[ch-1];
        if (ch < DD-1) a += w2*gap[ch+1];
        att[ch] = 1.f/(1.f+expf(-a));
    }
    __syncthreads();
    float* out = ((mode==0) ? g_text : (mode==1 ? g_vis : g_ac)) + (size_t)b*FLAT;
    for (int k = tid; k < FLAT; k += 384)
        out[k] = fetch(k) * att[k/NN];
}

// ---------------- means over n, cosine sims, routing mask ----------------
__global__ __launch_bounds__(256) void means_cos_kernel()
{
    int b = blockIdx.x, tid = threadIdx.x;
    __shared__ float mt[DD], mv[DD], ma[DD];
    const float* pt = g_text + (size_t)b*FLAT;
    const float* pv = g_vis  + (size_t)b*FLAT;
    const float* pa = g_ac   + (size_t)b*FLAT;
    for (int d = tid; d < DD; d += 256) {
        float st=0.f, sv=0.f, sa=0.f;
        for (int n = 0; n < NN; n++) {
            st += pt[n*DD+d]; sv += pv[n*DD+d]; sa += pa[n*DD+d];
        }
        st *= (1.f/NN); sv *= (1.f/NN); sa *= (1.f/NN);
        mt[d]=st; mv[d]=sv; ma[d]=sa;
        s_vmam32[(size_t)b*2*DD + d]      = f2tf32(sv);
        s_vmam32[(size_t)b*2*DD + DD + d] = f2tf32(sa);
    }
    __syncthreads();
    float p[6] = {0,0,0,0,0,0};  // tv, ta, va, tt, vv, aa
    for (int d = tid; d < DD; d += 256) {
        float t=mt[d], v=mv[d], a=ma[d];
        p[0]+=t*v; p[1]+=t*a; p[2]+=v*a; p[3]+=t*t; p[4]+=v*v; p[5]+=a*a;
    }
    __shared__ float red[256];
    __shared__ float res[6];
    for (int q = 0; q < 6; q++) {
        red[tid] = p[q]; __syncthreads();
        for (int s = 128; s > 0; s >>= 1) {
            if (tid < s) red[tid] += red[tid+s];
            __syncthreads();
        }
        if (tid == 0) res[q] = red[0];
        __syncthreads();
    }
    if (tid == 0) {
        float nt = fmaxf(sqrtf(res[3]), 1e-8f);
        float nv = fmaxf(sqrtf(res[4]), 1e-8f);
        float na = fmaxf(sqrtf(res[5]), 1e-8f);
        float rtv = res[0]/(nt*nv), rta = res[1]/(nt*na), rva = res[2]/(nv*na);
        float delta = (rtv + rta + rva) * (1.f/3.f);
        int mk;
        if (rtv > delta && rta > delta && rva > delta) mk = 0;       // f_concat
        else                                           mk = 2;       // f_cross
        s_mask[b] = mk;
    }
}

// ================= tf32 mma mainloop: R3 double-buffer + LDSM fragment loads =======
// 128x128 tile: acc += A[128,K] @ B[128,K]^T; operands tf32 in gmem. K % 32 == 0.
// Smem: A[128][36] + B[128][36] (pad 4 -> conflict-free STS.128 and ldmatrix).
__device__ __forceinline__ void mainloop_tf32(
    const uint32_t* __restrict__ Ab, const uint32_t* __restrict__ Bb, int K,
    uint32_t* Sh, float (&acc)[4][4][4])
{
    uint32_t (*As)[36] = reinterpret_cast<uint32_t(*)[36]>(Sh);
    uint32_t (*Bs)[36] = reinterpret_cast<uint32_t(*)[36]>(Sh + 4608);
    int tid  = threadIdx.x;
    int warp = tid >> 5, lane = tid & 31;
    int wm = (warp >> 2) * 64;
    int wn = (warp & 3) * 32;
    int lrow = tid >> 3;            // 0..31
    int lcol = (tid & 7) * 4;       // 0,4,...,28

    // ldmatrix per-lane source addresses
    int part = lane >> 3, row8 = lane & 7;
    uint32_t sA = smem_u32(As), sB = smem_u32(Bs);
    uint32_t aaddr[4], baddr[2];
    #pragma unroll
    for (int mi = 0; mi < 4; mi++)
        aaddr[mi] = sA + (((wm + mi*16 + (part & 1)*8 + row8)*36 + (part >> 1)*4) << 2);
    #pragma unroll
    for (int n2 = 0; n2 < 2; n2++)
        baddr[n2] = sB + (((wn + n2*16 + (part >> 1)*8 + row8)*36 + (part & 1)*4) << 2);

    uint4 aR[4], bR[4];
    auto ldg = [&](int k0){
        #pragma unroll
        for (int p = 0; p < 4; p++) {
            aR[p] = *reinterpret_cast<const uint4*>(Ab + (size_t)(p*32+lrow)*K + k0 + lcol);
            bR[p] = *reinterpret_cast<const uint4*>(Bb + (size_t)(p*32+lrow)*K + k0 + lcol);
        }
    };
    auto sts = [&](){
        #pragma unroll
        for (int p = 0; p < 4; p++) {
            int r = p*32 + lrow;
            *reinterpret_cast<uint4*>(&As[r][lcol]) = aR[p];
            *reinterpret_cast<uint4*>(&Bs[r][lcol]) = bR[p];
        }
    };

    ldg(0); sts();
    __syncthreads();

    for (int k0 = 32; k0 <= K; k0 += 32) {
        if (k0 < K) ldg(k0);
        #pragma unroll
        for (int kk8 = 0; kk8 < 4; kk8++) {
            uint32_t koff = kk8 * 32;   // 8 words * 4 bytes
            uint32_t af[4][4], bf_[4][2];
            #pragma unroll
            for (int mi = 0; mi < 4; mi++)
                asm volatile("ldmatrix.sync.aligned.m8n8.x4.shared.b16 {%0,%1,%2,%3}, [%4];"
                    : "=r"(af[mi][0]), "=r"(af[mi][1]), "=r"(af[mi][2]), "=r"(af[mi][3])
                    : "r"(aaddr[mi] + koff));
            #pragma unroll
            for (int n2 = 0; n2 < 2; n2++)
                asm volatile("ldmatrix.sync.aligned.m8n8.x4.shared.b16 {%0,%1,%2,%3}, [%4];"
                    : "=r"(bf_[2*n2][0]), "=r"(bf_[2*n2][1]),
                      "=r"(bf_[2*n2+1][0]), "=r"(bf_[2*n2+1][1])
                    : "r"(baddr[n2] + koff));
            #pragma unroll
            for (int mi = 0; mi < 4; mi++)
                #pragma unroll
                for (int ni = 0; ni < 4; ni++)
                    asm volatile(
                      "mma.sync.aligned.m16n8k8.row.col.f32.tf32.tf32.f32 "
                      "{%0,%1,%2,%3}, {%4,%5,%6,%7}, {%8,%9}, {%0,%1,%2,%3};"
                      : "+f"(acc[mi][ni][0]), "+f"(acc[mi][ni][1]),
                        "+f"(acc[mi][ni][2]), "+f"(acc[mi][ni][3])
                      : "r"(af[mi][0]), "r"(af[mi][1]), "r"(af[mi][2]), "r"(af[mi][3]),
                        "r"(bf_[ni][0]), "r"(bf_[ni][1]));
        }
        __syncthreads();
        if (k0 < K) { sts(); __syncthreads(); }
    }
}

// ---------------- generic GEMM: C[M,N] = (A@B^T + bias) * scale ------------------
__global__ __launch_bounds__(256,1) void gemm_tf32_v2(
    const uint32_t* __restrict__ A, const uint32_t* __restrict__ Bm, float* __restrict__ C,
    int Nn, int K, const float* __restrict__ bias, float out_scale)
{
    __shared__ __align__(16) uint32_t Sh[9216];
    float acc[4][4][4];
    #pragma unroll
    for (int i=0;i<4;i++) for (int j=0;j<4;j++) for (int r=0;r<4;r++) acc[i][j][r]=0.f;

    mainloop_tf32(A + (size_t)blockIdx.y*128*K, Bm + (size_t)blockIdx.x*128*K, K, Sh, acc);

    int tid = threadIdx.x;
    int warp = tid >> 5, lane = tid & 31;
    int wm = (warp >> 2) * 64, wn = (warp & 3) * 32;
    int g = lane >> 2, cq = lane & 3;
    int row0 = blockIdx.y*128 + wm;
    int col0 = blockIdx.x*128 + wn;
    #pragma unroll
    for (int mi = 0; mi < 4; mi++)
        #pragma unroll
        for (int ni = 0; ni < 4; ni++)
            #pragma unroll
            for (int r = 0; r < 4; r++) {
                int row = row0 + mi*16 + g + (r >> 1)*8;
                int n   = col0 + ni*8 + 2*cq + (r & 1);
                float v = acc[mi][ni][r];
                if (bias) v += bias[n];
                C[(size_t)row*Nn + n] = v * out_scale;
            }
}

// ---------------- recurrence GEMM with fused LSTM gate epilogue -------------------
__global__ __launch_bounds__(256,1) void gemm_lstm_step(int t, float* __restrict__ out)
{
    __shared__ __align__(16) uint32_t Sh[9216];
    float acc[4][4][4];
    #pragma unroll
    for (int i=0;i<4;i++) for (int j=0;j<4;j++) for (int r=0;r<4;r++) acc[i][j][r]=0.f;

    mainloop_tf32(s_h32 + (size_t)blockIdx.y*128*DD,
                  s_Whh32p + (size_t)blockIdx.x*128*DD, DD, Sh, acc);

    float* ebuf = (float*)Sh;           // 64 rows x 128 cols, XOR-swizzled
    int tid = threadIdx.x;
    int warp = tid >> 5, lane = tid & 31;
    int wm = (warp >> 2) * 64, wn = (warp & 3) * 32;
    int g = lane >> 2, cq = lane & 3;
    int jj_l = tid & 31, rgrp = tid >> 5;   // rgrp = warp id (0..7)

    #pragma unroll
    for (int hf = 0; hf < 2; hf++) {
        __syncthreads();
        if ((wm >> 6) == hf) {
            #pragma unroll
            for (int mi = 0; mi < 4; mi++)
                #pragma unroll
                for (int ni = 0; ni < 4; ni++) {
                    int c0 = wn + ni*8 + 2*cq;
                    int r0 = mi*16 + g;
                    *reinterpret_cast<float2*>(&ebuf[r0*128 + (c0 ^ ((r0&7)<<2))]) =
                        make_float2(acc[mi][ni][0], acc[mi][ni][1]);
                    int r1 = r0 + 8;
                    *reinterpret_cast<float2*>(&ebuf[r1*128 + (c0 ^ ((r1&7)<<2))]) =
                        make_float2(acc[mi][ni][2], acc[mi][ni][3]);
                }
        }
        __syncthreads();
        #pragma unroll
        for (int q = 0; q < 8; q++) {
            int r = rgrp + 8*q;                       // r&7 == rgrp
            int b = blockIdx.y*128 + hf*64 + r;
            int jjg = blockIdx.x*32 + jj_l;
            float4 acq = *reinterpret_cast<const float4*>(
                &ebuf[r*128 + ((4*jj_l) ^ (rgrp<<2))]);
            float4 xq = *reinterpret_cast<const float4*>(
                &s_xg[((size_t)b*NN + t)*D4 + blockIdx.x*128 + 4*jj_l]);
            float gi = acq.x + xq.x, gf = acq.y + xq.y;
            float gg = acq.z + xq.z, go = acq.w + xq.w;
            int ci = b*DD + jjg;
            float c = s_c[ci];
            float cn = fsig(gf)*c + fsig(gi)*ftanh(gg);
            s_c[ci] = cn;
            float hn = fsig(go)*ftanh(cn);
            s_h32[ci] = f2tf32(hn);
            size_t oo = ((size_t)b*NN + t)*DD + jjg;
            out[oo] = hn + g_text[oo];
        }
    }
}

// ---------------- LSTM step 0 (h=c=0): gates directly from xg ----------------
__global__ __launch_bounds__(256) void lstm_step0_kernel(float* __restrict__ out)
{
    int id = blockIdx.x*256 + threadIdx.x;   // < B*D
    int b = id / DD, jj = id - b*DD;
    float4 xq = *reinterpret_cast<const float4*>(&s_xg[((size_t)b*NN)*D4 + 4*jj]);
    float cn = fsig(xq.x) * ftanh(xq.z);
    s_c[id] = cn;
    float hn = fsig(xq.w) * ftanh(cn);
    s_h32[id] = f2tf32(hn);
    size_t oo = ((size_t)b*NN)*DD + jj;
    out[oo] = hn + g_text[oo];
}

// ---------------- fusion select + residual + LayerNorm -> shift (tf32) -------------
__global__ __launch_bounds__(256) void fusion_ln_kernel(
    const float* __restrict__ cW, const float* __restrict__ cb,
    const float* __restrict__ hW, const float* __restrict__ hb,
    const float* __restrict__ ln_g, const float* __restrict__ ln_b)
{
    int bn = blockIdx.x;           // b*50 + n
    int b = bn / NN;
    int tid = threadIdx.x;
    __shared__ float buf[DD];
    __shared__ float cat[3*DD];
    __shared__ float r1[256], r2[256];
    const float* txt = g_text + (size_t)bn*DD;
    int mk = s_mask[b];
    if (mk == 2) {
        const float* fc = s_fc + (size_t)b*DD;
        for (int d = tid; d < DD; d += 256) buf[d] = fc[d] + txt[d];
    } else {
        const float* pv = g_vis + (size_t)bn*DD;
        const float* pa = g_ac  + (size_t)bn*DD;
        for (int k = tid; k < DD; k += 256) {
            cat[k] = txt[k]; cat[DD+k] = pv[k]; cat[2*DD+k] = pa[k];
        }
        __syncthreads();
        for (int d = tid; d < DD; d += 256) {
            const float* wr = cW + (size_t)d*3*DD;
            float s = cb[d];
            for (int k = 0; k < 3*DD; k++) s += cat[k]*wr[k];
            buf[d] = s + txt[d];
        }
    }
    __syncthreads();
    float ps = 0.f;
    for (int d = tid; d < DD; d += 256) ps += buf[d];
    r1[tid] = ps; __syncthreads();
    for (int s = 128; s > 0; s >>= 1) { if (tid < s) r1[tid] += r1[tid+s]; __syncthreads(); }
    float mean = r1[0] * (1.f/DD);
    float pq = 0.f;
    for (int d = tid; d < DD; d += 256) { float x = buf[d]-mean; pq += x*x; }
    r2[tid] = pq; __syncthreads();
    for (int s = 128; s > 0; s >>= 1) { if (tid < s) r2[tid] += r2[tid+s]; __syncthreads(); }
    float rstd = rsqrtf(r2[0]*(1.f/DD) + 1e-5f);
    uint32_t* outp = s_shift32 + (size_t)bn*DD;
    for (int d = tid; d < DD; d += 256)
        outp[d] = f2tf32((buf[d]-mean)*rstd*ln_g[d] + ln_b[d]);
}

// ---------------- launch ----------------
extern "C" void kernel_launch(void* const* d_in, const int* in_sizes, int n_in,
                              void* d_out, int out_size)
{
    const float* text = (const float*)d_in[0];
    const int*   vids = (const int*)  d_in[1];
    const int*   aids = (const int*)  d_in[2];
    const float* vemb = (const float*)d_in[3];
    const float* aemb = (const float*)d_in[4];
    const float* w3   = (const float*)d_in[5];
    const float* Wih  = (const float*)d_in[6];
    const float* Whh  = (const float*)d_in[7];
    const float* bih  = (const float*)d_in[8];
    const float* bhh  = (const float*)d_in[9];
    const float* lng  = (const float*)d_in[10];
    const float* lnb  = (const float*)d_in[11];
    const float* cW   = (const float*)d_in[12];
    const float* cb   = (const float*)d_in[13];
    const float* hW   = (const float*)d_in[14];
    const float* hb   = (const float*)d_in[15];
    const float* vW   = (const float*)d_in[20];   // ca_vW [3,768,768]
    const float* vb   = (const float*)d_in[21];   // ca_vb [3,768]
    float* out = (float*)d_out;

    uint32_t *p_vmam32, *p_shift32, *p_vWc32, *p_Wih32p;
    float *p_fc, *p_vbsum, *p_xg, *p_bias_p;
    cudaGetSymbolAddress((void**)&p_vmam32, s_vmam32);
    cudaGetSymbolAddress((void**)&p_shift32, s_shift32);
    cudaGetSymbolAddress((void**)&p_vWc32, s_vWc32);
    cudaGetSymbolAddress((void**)&p_Wih32p, s_Wih32p);
    cudaGetSymbolAddress((void**)&p_fc, s_fc);
    cudaGetSymbolAddress((void**)&p_vbsum, s_vbsum);
    cudaGetSymbolAddress((void**)&p_xg, s_xg);
    cudaGetSymbolAddress((void**)&p_bias_p, s_bias_p);

    prep_kernel<<<(D4*DD + 255)/256, 256>>>(Wih, Whh, bih, bhh, vW, vb);
    egce_kernel<<<dim3(BB, 3), 384>>>(text, vids, aids, vemb, aemb, w3);
    means_cos_kernel<<<BB, 256>>>();

    // f_cross (single GEMM, K=1536): fc = ([vm|am] @ [vW0|W12]^T + vbsum) * (50/3)
    gemm_tf32_v2<<<dim3(DD/128, BB/128), 256>>>(
        p_vmam32, p_vWc32, p_fc, DD, 2*DD, p_vbsum, 50.f/3.f);

    fusion_ln_kernel<<<BB*NN, 256>>>(cW, cb, hW, hb, lng, lnb);

    // xg = shift @ Wih_perm^T + bias_perm   [25600, 3072] (gate-interleaved cols)
    gemm_tf32_v2<<<dim3(D4/128, (BB*NN)/128), 256>>>(
        p_shift32, p_Wih32p, p_xg, D4, DD, p_bias_p, 1.f);

    // LSTM: t=0 directly from xg; t=1..49 GEMM with fused gate epilogue
    lstm_step0_kernel<<<(BB*DD)/256, 256>>>(out);
    for (int t = 1; t < NN; t++)
        gemm_lstm_step<<<dim3(D4/128, BB/128), 256>>>(t, out);
}

// round 10
// speedup vs baseline: 1.8651x; 1.3499x over previous
#include <cuda_runtime.h>
#include <cuda_fp16.h>
#include <math.h>
#include <stdint.h>

#define BB 512
#define NN 50
#define DD 768
#define D4 3072
#define FLAT (NN*DD)   // 38400

#define ROWH 40                     // halves per smem row (32 data + 8 pad = 80B)
#define STAGE_H (128*ROWH)          // halves per operand per stage

// ---------------- scratch (__device__ globals; no allocation allowed) ----------------
__device__ float  g_text[BB*FLAT];
__device__ float  g_vis [BB*FLAT];
__device__ float  g_ac  [BB*FLAT];
__device__ __align__(16) __half s_shift16[BB*FLAT];     // fp16 LN output
__device__ float  s_xg[(size_t)BB*NN*D4];               // permuted gate pre-activations
__device__ __align__(16) __half s_h16a[BB*DD];          // hidden state ping
__device__ __align__(16) __half s_h16b[BB*DD];          // hidden state pong
__device__ float  s_c  [BB*DD];
__device__ __align__(16) __half s_vmam16[BB*2*DD];      // [b][vm|am]
__device__ float  s_fc [BB*DD];
__device__ __align__(16) __half s_Wih16p[(size_t)D4*DD];  // gate-interleaved rows
__device__ __align__(16) __half s_Whh16p[(size_t)D4*DD];
__device__ __align__(16) __half s_vWc16 [(size_t)DD*2*DD]; // [n][vW0|vW1+vW2]
__device__ float  s_bias_p[D4];                          // permuted bih+bhh
__device__ float  s_vbsum[DD];
__device__ int    s_mask[BB];

__device__ __forceinline__ float fsig(float x){
    return __fdividef(1.f, 1.f + __expf(-x));
}
__device__ __forceinline__ float ftanh(float x){
    return __fdividef(2.f, 1.f + __expf(-2.f*x)) - 1.f;
}
__device__ __forceinline__ uint32_t smem_u32(const void* p){
    uint32_t a;
    asm("{ .reg .u64 t; cvta.to.shared.u64 t, %1; cvt.u32.u64 %0, t; }"
        : "=r"(a) : "l"(p));
    return a;
}

// ---------------- prep: convert weights to fp16 (permuted), combine biases ----------
__global__ __launch_bounds__(256) void prep_kernel(
    const float* __restrict__ Wih, const float* __restrict__ Whh,
    const float* __restrict__ bih, const float* __restrict__ bhh,
    const float* __restrict__ vW,  const float* __restrict__ vb)
{
    int i = blockIdx.x*256 + threadIdx.x;
    if (i < D4*DD) {
        int p = i / DD, k = i - p*DD;
        int orig = (p & 3)*DD + (p >> 2);          // gate-interleave: p = 4*jj + gate
        s_Wih16p[i] = __float2half_rn(Wih[(size_t)orig*DD + k]);
        s_Whh16p[i] = __float2half_rn(Whh[(size_t)orig*DD + k]);
    }
    if (i < D4) {
        int orig = (i & 3)*DD + (i >> 2);
        s_bias_p[i] = bih[orig] + bhh[orig];
    }
    if (i < DD*DD) {
        int n = i / DD, k = i - n*DD;
        s_vWc16[(size_t)n*2*DD + k]      = __float2half_rn(vW[i]);
        s_vWc16[(size_t)n*2*DD + DD + k] =
            __float2half_rn(vW[DD*DD + i] + vW[2*DD*DD + i]);
    }
    if (i < DD) s_vbsum[i] = vb[i] + vb[DD+i] + vb[2*DD+i];
}

// ---------------- EGCE ----------------
__global__ __launch_bounds__(384) void egce_kernel(
    const float* __restrict__ text, const int* __restrict__ vids,
    const int* __restrict__ aids, const float* __restrict__ vemb,
    const float* __restrict__ aemb, const float* __restrict__ w3)
{
    int b = blockIdx.x;
    int mode = blockIdx.y;     // 0=text, 1=visual(relu gather), 2=acoustic(gather)
    int tid = threadIdx.x;
    __shared__ float gap[DD];
    __shared__ float att[DD];
    __shared__ int ids[NN];
    if (tid < NN)
        ids[tid] = (mode==1) ? vids[b*NN+tid] : (mode==2 ? aids[b*NN+tid] : 0);
    __syncthreads();

    const float* src = (mode==0) ? (text + (size_t)b*FLAT) : (mode==1 ? vemb : aemb);

    auto fetch = [&](int k)->float {
        if (mode == 0) return src[k];
        int n = k / DD; int d = k - n*DD;
        float v = src[(size_t)ids[n]*DD + d];
        if (mode == 1) v = fmaxf(v, 0.f);
        return v;
    };

    for (int ch = tid; ch < DD; ch += 384) {
        float s = 0.f; int base = ch*NN;
        #pragma unroll 5
        for (int j = 0; j < NN; j++) s += fetch(base+j);
        gap[ch] = s * (1.f/NN);
    }
    __syncthreads();
    float w0 = w3[0], w1 = w3[1], w2 = w3[2];
    for (int ch = tid; ch < DD; ch += 384) {
        float a = w1*gap[ch];
        if (ch > 0)    a += w0*gap[ch-1];
        if (ch < DD-1) a += w2*gap[ch+1];
        att[ch] = 1.f/(1.f+expf(-a));
    }
    __syncthreads();
    float* out = ((mode==0) ? g_text : (mode==1 ? g_vis : g_ac)) + (size_t)b*FLAT;
    for (int k = tid; k < FLAT; k += 384)
        out[k] = fetch(k) * att[k/NN];
}

// ---------------- means over n, cosine sims, routing mask ----------------
__global__ __launch_bounds__(256) void means_cos_kernel()
{
    int b = blockIdx.x, tid = threadIdx.x;
    __shared__ float mt[DD], mv[DD], ma[DD];
    const float* pt = g_text + (size_t)b*FLAT;
    const float* pv = g_vis  + (size_t)b*FLAT;
    const float* pa = g_ac   + (size_t)b*FLAT;
    for (int d = tid; d < DD; d += 256) {
        float st=0.f, sv=0.f, sa=0.f;
        for (int n = 0; n < NN; n++) {
            st += pt[n*DD+d]; sv += pv[n*DD+d]; sa += pa[n*DD+d];
        }
        st *= (1.f/NN); sv *= (1.f/NN); sa *= (1.f/NN);
        mt[d]=st; mv[d]=sv; ma[d]=sa;
        s_vmam16[(size_t)b*2*DD + d]      = __float2half_rn(sv);
        s_vmam16[(size_t)b*2*DD + DD + d] = __float2half_rn(sa);
    }
    __syncthreads();
    float p[6] = {0,0,0,0,0,0};  // tv, ta, va, tt, vv, aa
    for (int d = tid; d < DD; d += 256) {
        float t=mt[d], v=mv[d], a=ma[d];
        p[0]+=t*v; p[1]+=t*a; p[2]+=v*a; p[3]+=t*t; p[4]+=v*v; p[5]+=a*a;
    }
    __shared__ float red[256];
    __shared__ float res[6];
    for (int q = 0; q < 6; q++) {
        red[tid] = p[q]; __syncthreads();
        for (int s = 128; s > 0; s >>= 1) {
            if (tid < s) red[tid] += red[tid+s];
            __syncthreads();
        }
        if (tid == 0) res[q] = red[0];
        __syncthreads();
    }
    if (tid == 0) {
        float nt = fmaxf(sqrtf(res[3]), 1e-8f);
        float nv = fmaxf(sqrtf(res[4]), 1e-8f);
        float na = fmaxf(sqrtf(res[5]), 1e-8f);
        float rtv = res[0]/(nt*nv), rta = res[1]/(nt*na), rva = res[2]/(nv*na);
        float delta = (rtv + rta + rva) * (1.f/3.f);
        int mk;
        if (rtv > delta && rta > delta && rva > delta) mk = 0;       // f_concat
        else                                           mk = 2;       // f_cross
        s_mask[b] = mk;
    }
}

// ================= fp16 mma mainloop: 2-stage cp.async + ldmatrix ==================
// 128x128 tile: acc += A[128,K] @ B[128,K]^T; fp16 operands, fp32 accum. K%32==0.
// Smem rows padded to 40 halves (80B): ldmatrix quad = (5r+p) mod 8 -> conflict-free.
__device__ __forceinline__ void mainloop_f16(
    const __half* __restrict__ Ab, const __half* __restrict__ Bb, int K,
    __half* Sh, float (&acc)[4][4][4])
{
    int tid  = threadIdx.x;
    int lane = tid & 31, warp = tid >> 5;
    int wm = (warp >> 2) * 64;
    int wn = (warp & 3) * 32;
    int ntiles = K >> 5;

    // ldmatrix per-lane offsets (in halves, relative to stage A/B base)
    int part = lane >> 3, row8 = lane & 7;
    uint32_t offA[4], offB[2];
    #pragma unroll
    for (int mi = 0; mi < 4; mi++) {
        int r = wm + mi*16 + (part & 1)*8 + row8;
        offA[mi] = (uint32_t)(r*ROWH + (part >> 1)*8) * 2;   // bytes
    }
    #pragma unroll
    for (int n2 = 0; n2 < 2; n2++) {
        int r = wn + n2*16 + (part >> 1)*8 + row8;
        offB[n2] = (uint32_t)(r*ROWH + (part & 1)*8) * 2;
    }
    uint32_t sbase = smem_u32(Sh);

    auto issue = [&](int kt, int s){
        __half* As = Sh + s*2*STAGE_H;
        __half* Bs = As + STAGE_H;
        #pragma unroll
        for (int i = 0; i < 2; i++) {
            int q = tid + i*256;            // 0..511
            int row = q >> 2, c = q & 3;
            uint32_t da = smem_u32(As + row*ROWH + c*8);
            uint32_t db = smem_u32(Bs + row*ROWH + c*8);
            const __half* ga = Ab + (size_t)row*K + kt*32 + c*8;
            const __half* gb = Bb + (size_t)row*K + kt*32 + c*8;
            asm volatile("cp.async.cg.shared.global [%0], [%1], 16;"
                         :: "r"(da), "l"(ga) : "memory");
            asm volatile("cp.async.cg.shared.global [%0], [%1], 16;"
                         :: "r"(db), "l"(gb) : "memory");
        }
        asm volatile("cp.async.commit_group;" ::: "memory");
    };

    issue(0, 0);
    for (int kt = 0; kt < ntiles; kt++) {
        if (kt + 1 < ntiles) {
            issue(kt + 1, (kt + 1) & 1);
            asm volatile("cp.async.wait_group 1;" ::: "memory");
        } else {
            asm volatile("cp.async.wait_group 0;" ::: "memory");
        }
        __syncthreads();

        uint32_t abase = sbase + (uint32_t)(kt & 1)*2*STAGE_H*2;
        uint32_t bbase = abase + STAGE_H*2;
        #pragma unroll
        for (int kk = 0; kk < 2; kk++) {          // two k16 groups per 32-chunk
            uint32_t koff = kk * 32;              // 16 halves = 32 bytes
            uint32_t a[4][4], bfr[4][2];
            #pragma unroll
            for (int mi = 0; mi < 4; mi++)
                asm volatile("ldmatrix.sync.aligned.m8n8.x4.shared.b16 "
                    "{%0,%1,%2,%3}, [%4];"
                    : "=r"(a[mi][0]), "=r"(a[mi][1]), "=r"(a[mi][2]), "=r"(a[mi][3])
                    : "r"(abase + offA[mi] + koff));
            #pragma unroll
            for (int n2 = 0; n2 < 2; n2++)
                asm volatile("ldmatrix.sync.aligned.m8n8.x4.shared.b16 "
                    "{%0,%1,%2,%3}, [%4];"
                    : "=r"(bfr[2*n2][0]), "=r"(bfr[2*n2][1]),
                      "=r"(bfr[2*n2+1][0]), "=r"(bfr[2*n2+1][1])
                    : "r"(bbase + offB[n2] + koff));
            #pragma unroll
            for (int mi = 0; mi < 4; mi++)
                #pragma unroll
                for (int ni = 0; ni < 4; ni++)
                    asm volatile(
                      "mma.sync.aligned.m16n8k16.row.col.f32.f16.f16.f32 "
                      "{%0,%1,%2,%3}, {%4,%5,%6,%7}, {%8,%9}, {%0,%1,%2,%3};"
                      : "+f"(acc[mi][ni][0]), "+f"(acc[mi][ni][1]),
                        "+f"(acc[mi][ni][2]), "+f"(acc[mi][ni][3])
                      : "r"(a[mi][0]), "r"(a[mi][1]), "r"(a[mi][2]), "r"(a[mi][3]),
                        "r"(bfr[ni][0]), "r"(bfr[ni][1]));
        }
        __syncthreads();
    }
}

// ---------------- generic GEMM: C[M,N] = (A@B^T + bias) * scale ------------------
__global__ __launch_bounds__(256,2) void gemm_f16(
    const __half* __restrict__ A, const __half* __restrict__ Bm, float* __restrict__ C,
    int Nn, int K, const float* __restrict__ bias, float out_scale)
{
    __shared__ __align__(16) __half Sh[4*STAGE_H];
    float acc[4][4][4];
    #pragma unroll
    for (int i=0;i<4;i++) for (int j=0;j<4;j++) for (int r=0;r<4;r++) acc[i][j][r]=0.f;

    mainloop_f16(A + (size_t)blockIdx.y*128*K, Bm + (size_t)blockIdx.x*128*K, K, Sh, acc);

    int tid = threadIdx.x;
    int warp = tid >> 5, lane = tid & 31;
    int wm = (warp >> 2) * 64, wn = (warp & 3) * 32;
    int g = lane >> 2, cq = lane & 3;
    int row0 = blockIdx.y*128 + wm;
    int col0 = blockIdx.x*128 + wn;
    #pragma unroll
    for (int mi = 0; mi < 4; mi++)
        #pragma unroll
        for (int ni = 0; ni < 4; ni++)
            #pragma unroll
            for (int r = 0; r < 4; r++) {
                int row = row0 + mi*16 + g + (r >> 1)*8;
                int n   = col0 + ni*8 + 2*cq + (r & 1);
                float v = acc[mi][ni][r];
                if (bias) v += bias[n];
                C[(size_t)row*Nn + n] = v * out_scale;
            }
}

// ---------------- recurrence GEMM with fused LSTM gate epilogue -------------------
__global__ __launch_bounds__(256,2) void gemm_lstm_step(
    int t, const __half* __restrict__ hin, __half* __restrict__ hout,
    float* __restrict__ out)
{
    __shared__ __align__(16) __half Sh[4*STAGE_H];
    float acc[4][4][4];
    #pragma unroll
    for (int i=0;i<4;i++) for (int j=0;j<4;j++) for (int r=0;r<4;r++) acc[i][j][r]=0.f;

    mainloop_f16(hin + (size_t)blockIdx.y*128*DD,
                 s_Whh16p + (size_t)blockIdx.x*128*DD, DD, Sh, acc);

    float* ebuf = (float*)Sh;           // 64 rows x 128 cols, XOR-swizzled (32KB)
    int tid = threadIdx.x;
    int warp = tid >> 5, lane = tid & 31;
    int wm = (warp >> 2) * 64, wn = (warp & 3) * 32;
    int g = lane >> 2, cq = lane & 3;
    int jj_l = tid & 31, rgrp = tid >> 5;   // rgrp = warp id (0..7)

    #pragma unroll
    for (int hf = 0; hf < 2; hf++) {
        __syncthreads();
        if ((wm >> 6) == hf) {
            #pragma unroll
            for (int mi = 0; mi < 4; mi++)
                #pragma unroll
                for (int ni = 0; ni < 4; ni++) {
                    int c0 = wn + ni*8 + 2*cq;
                    int r0 = mi*16 + g;
                    *reinterpret_cast<float2*>(&ebuf[r0*128 + (c0 ^ ((r0&7)<<2))]) =
                        make_float2(acc[mi][ni][0], acc[mi][ni][1]);
                    int r1 = r0 + 8;
                    *reinterpret_cast<float2*>(&ebuf[r1*128 + (c0 ^ ((r1&7)<<2))]) =
                        make_float2(acc[mi][ni][2], acc[mi][ni][3]);
                }
        }
        __syncthreads();
        #pragma unroll
        for (int q = 0; q < 8; q++) {
            int r = rgrp + 8*q;                       // r&7 == rgrp
            int b = blockIdx.y*128 + hf*64 + r;
            int jjg = blockIdx.x*32 + jj_l;
            float4 acq = *reinterpret_cast<const float4*>(
                &ebuf[r*128 + ((4*jj_l) ^ (rgrp<<2))]);
            float4 xq = *reinterpret_cast<const float4*>(
                &s_xg[((size_t)b*NN + t)*D4 + blockIdx.x*128 + 4*jj_l]);
            float gi = acq.x + xq.x, gf = acq.y + xq.y;
            float gg = acq.z + xq.z, go = acq.w + xq.w;
            int ci = b*DD + jjg;
            float c = s_c[ci];
            float cn = fsig(gf)*c + fsig(gi)*ftanh(gg);
            s_c[ci] = cn;
            float hn = fsig(go)*ftanh(cn);
            hout[ci] = __float2half_rn(hn);
            size_t oo = ((size_t)b*NN + t)*DD + jjg;
            out[oo] = hn + g_text[oo];
        }
    }
}

// ---------------- LSTM step 0 (h=c=0): gates directly from xg ----------------
__global__ __launch_bounds__(256) void lstm_step0_kernel(float* __restrict__ out)
{
    int id = blockIdx.x*256 + threadIdx.x;   // < B*D
    int b = id / DD, jj = id - b*DD;
    float4 xq = *reinterpret_cast<const float4*>(&s_xg[((size_t)b*NN)*D4 + 4*jj]);
    float cn = fsig(xq.x) * ftanh(xq.z);
    s_c[id] = cn;
    float hn = fsig(xq.w) * ftanh(cn);
    s_h16a[id] = __float2half_rn(hn);
    size_t oo = ((size_t)b*NN)*DD + jj;
    out[oo] = hn + g_text[oo];
}

// ---------------- fusion select + residual + LayerNorm -> shift (fp16) -------------
__global__ __launch_bounds__(256) void fusion_ln_kernel(
    const float* __restrict__ cW, const float* __restrict__ cb,
    const float* __restrict__ hW, const float* __restrict__ hb,
    const float* __restrict__ ln_g, const float* __restrict__ ln_b)
{
    int bn = blockIdx.x;           // b*50 + n
    int b = bn / NN;
    int tid = threadIdx.x;
    __shared__ float buf[DD];
    __shared__ float cat[3*DD];
    __shared__ float r1[256], r2[256];
    const float* txt = g_text + (size_t)bn*DD;
    int mk = s_mask[b];
    if (mk == 2) {
        const float* fc = s_fc + (size_t)b*DD;
        for (int d = tid; d < DD; d += 256) buf[d] = fc[d] + txt[d];
    } else {
        const float* pv = g_vis + (size_t)bn*DD;
        const float* pa = g_ac  + (size_t)bn*DD;
        for (int k = tid; k < DD; k += 256) {
            cat[k] = txt[k]; cat[DD+k] = pv[k]; cat[2*DD+k] = pa[k];
        }
        __syncthreads();
        for (int d = tid; d < DD; d += 256) {
            const float* wr = cW + (size_t)d*3*DD;
            float s = cb[d];
            for (int k = 0; k < 3*DD; k++) s += cat[k]*wr[k];
            buf[d] = s + txt[d];
        }
    }
    __syncthreads();
    float ps = 0.f;
    for (int d = tid; d < DD; d += 256) ps += buf[d];
    r1[tid] = ps; __syncthreads();
    for (int s = 128; s > 0; s >>= 1) { if (tid < s) r1[tid] += r1[tid+s]; __syncthreads(); }
    float mean = r1[0] * (1.f/DD);
    float pq = 0.f;
    for (int d = tid; d < DD; d += 256) { float x = buf[d]-mean; pq += x*x; }
    r2[tid] = pq; __syncthreads();
    for (int s = 128; s > 0; s >>= 1) { if (tid < s) r2[tid] += r2[tid+s]; __syncthreads(); }
    float rstd = rsqrtf(r2[0]*(1.f/DD) + 1e-5f);
    __half* outp = s_shift16 + (size_t)bn*DD;
    for (int d = tid; d < DD; d += 256)
        outp[d] = __float2half_rn((buf[d]-mean)*rstd*ln_g[d] + ln_b[d]);
}

// ---------------- launch ----------------
extern "C" void kernel_launch(void* const* d_in, const int* in_sizes, int n_in,
                              void* d_out, int out_size)
{
    const float* text = (const float*)d_in[0];
    const int*   vids = (const int*)  d_in[1];
    const int*   aids = (const int*)  d_in[2];
    const float* vemb = (const float*)d_in[3];
    const float* aemb = (const float*)d_in[4];
    const float* w3   = (const float*)d_in[5];
    const float* Wih  = (const float*)d_in[6];
    const float* Whh  = (const float*)d_in[7];
    const float* bih  = (const float*)d_in[8];
    const float* bhh  = (const float*)d_in[9];
    const float* lng  = (const float*)d_in[10];
    const float* lnb  = (const float*)d_in[11];
    const float* cW   = (const float*)d_in[12];
    const float* cb   = (const float*)d_in[13];
    const float* hW   = (const float*)d_in[14];
    const float* hb   = (const float*)d_in[15];
    const float* vW   = (const float*)d_in[20];   // ca_vW [3,768,768]
    const float* vb   = (const float*)d_in[21];   // ca_vb [3,768]
    float* out = (float*)d_out;

    __half *p_vmam16, *p_shift16, *p_vWc16, *p_Wih16p, *p_ha, *p_hb;
    float *p_fc, *p_vbsum, *p_xg, *p_bias_p;
    cudaGetSymbolAddress((void**)&p_vmam16, s_vmam16);
    cudaGetSymbolAddress((void**)&p_shift16, s_shift16);
    cudaGetSymbolAddress((void**)&p_vWc16, s_vWc16);
    cudaGetSymbolAddress((void**)&p_Wih16p, s_Wih16p);
    cudaGetSymbolAddress((void**)&p_ha, s_h16a);
    cudaGetSymbolAddress((void**)&p_hb, s_h16b);
    cudaGetSymbolAddress((void**)&p_fc, s_fc);
    cudaGetSymbolAddress((void**)&p_vbsum, s_vbsum);
    cudaGetSymbolAddress((void**)&p_xg, s_xg);
    cudaGetSymbolAddress((void**)&p_bias_p, s_bias_p);

    prep_kernel<<<(D4*DD + 255)/256, 256>>>(Wih, Whh, bih, bhh, vW, vb);
    egce_kernel<<<dim3(BB, 3), 384>>>(text, vids, aids, vemb, aemb, w3);
    means_cos_kernel<<<BB, 256>>>();

    // f_cross (single GEMM, K=1536): fc = ([vm|am] @ [vW0|W12]^T + vbsum) * (50/3)
    gemm_f16<<<dim3(DD/128, BB/128), 256>>>(
        p_vmam16, p_vWc16, p_fc, DD, 2*DD, p_vbsum, 50.f/3.f);

    fusion_ln_kernel<<<BB*NN, 256>>>(cW, cb, hW, hb, lng, lnb);

    // xg = shift @ Wih_perm^T + bias_perm   [25600, 3072] (gate-interleaved cols)
    gemm_f16<<<dim3(D4/128, (BB*NN)/128), 256>>>(
        p_shift16, p_Wih16p, p_xg, D4, DD, p_bias_p, 1.f);

    // LSTM: t=0 directly from xg; t=1..49 GEMM with fused gate epilogue.
    // h double-buffered across steps (step t reads buf[(t-1)&1], writes buf[t&1]).
    lstm_step0_kernel<<<(BB*DD)/256, 256>>>(out);
    for (int t = 1; t < NN; t++) {
        __half* hin  = ((t-1) & 1) ? p_hb : p_ha;
        __half* hout = (t & 1)     ? p_hb : p_ha;
        gemm_lstm_step<<<dim3(D4/128, BB/128), 256>>>(t, hin, hout, out);
    }
}

// round 11
// speedup vs baseline: 2.0011x; 1.0729x over previous
#include <cuda_runtime.h>
#include <cuda_fp16.h>
#include <math.h>
#include <stdint.h>

#define BB 512
#define NN 50
#define DD 768
#define D4 3072
#define FLAT (NN*DD)   // 38400

#define ROWH 40                     // halves per A/B smem row in generic gemm (80B)
#define STAGE_H (128*ROWH)

// persistent LSTM kernel smem plan
#define PAD_B 776                   // halves per resident-B row (1552B: 16B-mult, bank step 4)
#define PRS_BH (128*PAD_B)          // 99328 halves = 198656 B
#define A_ST_H (128*ROWH)           // 5120 halves per A stage
#define PRS_REGION_B 32768          // union: 3 A-stages (30720B) / ebuf (32768B)
#define PRS_SMEM (PRS_BH*2 + PRS_REGION_B)   // 231424 B

// ---------------- scratch (__device__ globals; no allocation allowed) ----------------
__device__ float  g_text[BB*FLAT];
__device__ __align__(16) __half s_shift16[BB*FLAT];
__device__ __align__(16) __half s_xg16[(size_t)BB*NN*D4];   // permuted gate pre-acts
__device__ __align__(16) __half s_h16a[BB*DD];
__device__ __align__(16) __half s_h16b[BB*DD];
__device__ float  s_c  [BB*DD];
__device__ __align__(16) __half s_vmam16[BB*2*DD];          // [b][vm|am]
__device__ float  s_fc [BB*DD];
__device__ __align__(16) __half s_Wih16p[(size_t)D4*DD];    // gate-interleaved rows
__device__ __align__(16) __half s_Whh16p[(size_t)D4*DD];
__device__ __align__(16) __half s_vWc16 [(size_t)DD*2*DD];  // [n][vW0|vW1+vW2]
__device__ float  s_bias_p[D4];
__device__ float  s_vbsum[DD];
__device__ int    g_cnt;
__device__ int    g_gen;

__device__ __forceinline__ float fsig(float x){
    return __fdividef(1.f, 1.f + __expf(-x));
}
__device__ __forceinline__ float ftanh(float x){
    return __fdividef(2.f, 1.f + __expf(-2.f*x)) - 1.f;
}
__device__ __forceinline__ uint32_t smem_u32(const void* p){
    uint32_t a;
    asm("{ .reg .u64 t; cvta.to.shared.u64 t, %1; cvt.u32.u64 %0, t; }"
        : "=r"(a) : "l"(p));
    return a;
}

// ---------------- prep: convert weights to fp16 (permuted), combine biases ----------
__global__ __launch_bounds__(256) void prep_kernel(
    const float* __restrict__ Wih, const float* __restrict__ Whh,
    const float* __restrict__ bih, const float* __restrict__ bhh,
    const float* __restrict__ vW,  const float* __restrict__ vb)
{
    int i = blockIdx.x*256 + threadIdx.x;
    if (i < D4*DD) {
        int p = i / DD, k = i - p*DD;
        int orig = (p & 3)*DD + (p >> 2);          // gate-interleave: p = 4*jj + gate
        s_Wih16p[i] = __float2half_rn(Wih[(size_t)orig*DD + k]);
        s_Whh16p[i] = __float2half_rn(Whh[(size_t)orig*DD + k]);
    }
    if (i < D4) {
        int orig = (i & 3)*DD + (i >> 2);
        s_bias_p[i] = bih[orig] + bhh[orig];
    }
    if (i < DD*DD) {
        int n = i / DD, k = i - n*DD;
        s_vWc16[(size_t)n*2*DD + k]      = __float2half_rn(vW[i]);
        s_vWc16[(size_t)n*2*DD + DD + k] =
            __float2half_rn(vW[DD*DD + i] + vW[2*DD*DD + i]);
    }
    if (i < DD) s_vbsum[i] = vb[i] + vb[DD+i] + vb[2*DD+i];
}

// ---------------- EGCE text: gate + write g_text ----------------
__global__ __launch_bounds__(384) void egce_text(
    const float* __restrict__ text, const float* __restrict__ w3)
{
    int b = blockIdx.x, tid = threadIdx.x;
    __shared__ float gap[DD], att[DD];
    const float* src = text + (size_t)b*FLAT;
    for (int ch = tid; ch < DD; ch += 384) {
        float s = 0.f; int base = ch*NN;
        #pragma unroll 5
        for (int j = 0; j < NN; j++) s += src[base+j];
        gap[ch] = s * (1.f/NN);
    }
    __syncthreads();
    float w0 = w3[0], w1 = w3[1], w2 = w3[2];
    for (int ch = tid; ch < DD; ch += 384) {
        float a = w1*gap[ch];
        if (ch > 0)    a += w0*gap[ch-1];
        if (ch < DD-1) a += w2*gap[ch+1];
        att[ch] = 1.f/(1.f+expf(-a));
    }
    __syncthreads();
    float* out = g_text + (size_t)b*FLAT;
    for (int k = tid; k < FLAT; k += 384)
        out[k] = src[k] * att[k/NN];
}

// ---------------- EGCE visual/acoustic: gated means straight from tables -----------
// vm[b,d] = (1/50) * sum_n relu?(emb[ids[n],d]) * att[(n*768+d)/50]
__global__ __launch_bounds__(256) void egce_va(
    const int* __restrict__ vids, const int* __restrict__ aids,
    const float* __restrict__ vemb, const float* __restrict__ aemb,
    const float* __restrict__ w3)
{
    int b = blockIdx.x;
    int mode = blockIdx.y;        // 0=visual(relu), 1=acoustic
    int tid = threadIdx.x;
    __shared__ int ids[NN];
    __shared__ float gap[DD], att[DD];
    if (tid < NN)
        ids[tid] = mode ? aids[b*NN+tid] : vids[b*NN+tid];
    __syncthreads();
    const float* emb = mode ? aemb : vemb;

    for (int ch = tid; ch < DD; ch += 256) {
        float s = 0.f; int base = ch*NN;
        for (int j = 0; j < NN; j++) {
            int k = base + j;
            int n = k / DD, d = k - n*DD;
            float v = emb[(size_t)ids[n]*DD + d];
            if (!mode) v = fmaxf(v, 0.f);
            s += v;
        }
        gap[ch] = s * (1.f/NN);
    }
    __syncthreads();
    float w0 = w3[0], w1 = w3[1], w2 = w3[2];
    for (int ch = tid; ch < DD; ch += 256) {
        float a = w1*gap[ch];
        if (ch > 0)    a += w0*gap[ch-1];
        if (ch < DD-1) a += w2*gap[ch+1];
        att[ch] = 1.f/(1.f+expf(-a));
    }
    __syncthreads();
    for (int d = tid; d < DD; d += 256) {
        float acc = 0.f;
        for (int n = 0; n < NN; n++) {
            float v = emb[(size_t)ids[n]*DD + d];
            if (!mode) v = fmaxf(v, 0.f);
            acc += v * att[(n*DD + d)/NN];
        }
        s_vmam16[(size_t)b*2*DD + mode*DD + d] = __float2half_rn(acc * (1.f/NN));
    }
}

// ================= fp16 mma mainloop (generic): 2-stage cp.async + ldmatrix ========
__device__ __forceinline__ void mainloop_f16(
    const __half* __restrict__ Ab, const __half* __restrict__ Bb, int K,
    __half* Sh, float (&acc)[4][4][4])
{
    int tid  = threadIdx.x;
    int lane = tid & 31, warp = tid >> 5;
    int wm = (warp >> 2) * 64;
    int wn = (warp & 3) * 32;
    int ntiles = K >> 5;

    int part = lane >> 3, row8 = lane & 7;
    uint32_t offA[4], offB[2];
    #pragma unroll
    for (int mi = 0; mi < 4; mi++) {
        int r = wm + mi*16 + (part & 1)*8 + row8;
        offA[mi] = (uint32_t)(r*ROWH + (part >> 1)*8) * 2;
    }
    #pragma unroll
    for (int n2 = 0; n2 < 2; n2++) {
        int r = wn + n2*16 + (part >> 1)*8 + row8;
        offB[n2] = (uint32_t)(r*ROWH + (part & 1)*8) * 2;
    }
    uint32_t sbase = smem_u32(Sh);

    auto issue = [&](int kt, int s){
        __half* As = Sh + s*2*STAGE_H;
        __half* Bs = As + STAGE_H;
        #pragma unroll
        for (int i = 0; i < 2; i++) {
            int q = tid + i*256;
            int row = q >> 2, c = q & 3;
            uint32_t da = smem_u32(As + row*ROWH + c*8);
            uint32_t db = smem_u32(Bs + row*ROWH + c*8);
            const __half* ga = Ab + (size_t)row*K + kt*32 + c*8;
            const __half* gb = Bb + (size_t)row*K + kt*32 + c*8;
            asm volatile("cp.async.cg.shared.global [%0], [%1], 16;"
                         :: "r"(da), "l"(ga) : "memory");
            asm volatile("cp.async.cg.shared.global [%0], [%1], 16;"
                         :: "r"(db), "l"(gb) : "memory");
        }
        asm volatile("cp.async.commit_group;" ::: "memory");
    };

    issue(0, 0);
    for (int kt = 0; kt < ntiles; kt++) {
        if (kt + 1 < ntiles) {
            issue(kt + 1, (kt + 1) & 1);
            asm volatile("cp.async.wait_group 1;" ::: "memory");
        } else {
            asm volatile("cp.async.wait_group 0;" ::: "memory");
        }
        __syncthreads();

        uint32_t abase = sbase + (uint32_t)(kt & 1)*2*STAGE_H*2;
        uint32_t bbase = abase + STAGE_H*2;
        #pragma unroll
        for (int kk = 0; kk < 2; kk++) {
            uint32_t koff = kk * 32;
            uint32_t a[4][4], bfr[4][2];
            #pragma unroll
            for (int mi = 0; mi < 4; mi++)
                asm volatile("ldmatrix.sync.aligned.m8n8.x4.shared.b16 "
                    "{%0,%1,%2,%3}, [%4];"
                    : "=r"(a[mi][0]), "=r"(a[mi][1]), "=r"(a[mi][2]), "=r"(a[mi][3])
                    : "r"(abase + offA[mi] + koff));
            #pragma unroll
            for (int n2 = 0; n2 < 2; n2++)
                asm volatile("ldmatrix.sync.aligned.m8n8.x4.shared.b16 "
                    "{%0,%1,%2,%3}, [%4];"
                    : "=r"(bfr[2*n2][0]), "=r"(bfr[2*n2][1]),
                      "=r"(bfr[2*n2+1][0]), "=r"(bfr[2*n2+1][1])
                    : "r"(bbase + offB[n2] + koff));
            #pragma unroll
            for (int mi = 0; mi < 4; mi++)
                #pragma unroll
                for (int ni = 0; ni < 4; ni++)
                    asm volatile(
                      "mma.sync.aligned.m16n8k16.row.col.f32.f16.f16.f32 "
                      "{%0,%1,%2,%3}, {%4,%5,%6,%7}, {%8,%9}, {%0,%1,%2,%3};"
                      : "+f"(acc[mi][ni][0]), "+f"(acc[mi][ni][1]),
                        "+f"(acc[mi][ni][2]), "+f"(acc[mi][ni][3])
                      : "r"(a[mi][0]), "r"(a[mi][1]), "r"(a[mi][2]), "r"(a[mi][3]),
                        "r"(bfr[ni][0]), "r"(bfr[ni][1]));
        }
        __syncthreads();
    }
}

// ---------------- generic GEMM: C = (A@B^T + bias)*scale; fp32 or fp16 out ---------
__global__ __launch_bounds__(256,2) void gemm_f16(
    const __half* __restrict__ A, const __half* __restrict__ Bm,
    float* __restrict__ Cf, __half* __restrict__ Ch,
    int Nn, int K, const float* __restrict__ bias, float out_scale)
{
    __shared__ __align__(16) __half Sh[4*STAGE_H];
    float acc[4][4][4];
    #pragma unroll
    for (int i=0;i<4;i++) for (int j=0;j<4;j++) for (int r=0;r<4;r++) acc[i][j][r]=0.f;

    mainloop_f16(A + (size_t)blockIdx.y*128*K, Bm + (size_t)blockIdx.x*128*K, K, Sh, acc);

    int tid = threadIdx.x;
    int warp = tid >> 5, lane = tid & 31;
    int wm = (warp >> 2) * 64, wn = (warp & 3) * 32;
    int g = lane >> 2, cq = lane & 3;
    int row0 = blockIdx.y*128 + wm;
    int col0 = blockIdx.x*128 + wn;
    #pragma unroll
    for (int mi = 0; mi < 4; mi++)
        #pragma unroll
        for (int ni = 0; ni < 4; ni++) {
            int ra = row0 + mi*16 + g;
            int rb = ra + 8;
            int n0 = col0 + ni*8 + 2*cq;
            float v0 = (acc[mi][ni][0] + bias[n0])   * out_scale;
            float v1 = (acc[mi][ni][1] + bias[n0+1]) * out_scale;
            float v2 = (acc[mi][ni][2] + bias[n0])   * out_scale;
            float v3 = (acc[mi][ni][3] + bias[n0+1]) * out_scale;
            if (Ch) {
                *(__half2*)&Ch[(size_t)ra*Nn + n0] = __floats2half2_rn(v0, v1);
                *(__half2*)&Ch[(size_t)rb*Nn + n0] = __floats2half2_rn(v2, v3);
            } else {
                Cf[(size_t)ra*Nn + n0]   = v0;
                Cf[(size_t)ra*Nn + n0+1] = v1;
                Cf[(size_t)rb*Nn + n0]   = v2;
                Cf[(size_t)rb*Nn + n0+1] = v3;
            }
        }
}

// ---------------- fusion (always f_cross) + residual + LayerNorm -> shift ----------
__global__ __launch_bounds__(256) void fusion_ln_kernel(
    const float* __restrict__ ln_g, const float* __restrict__ ln_b)
{
    int bn = blockIdx.x;           // b*50 + n
    int b = bn / NN;
    int tid = threadIdx.x;
    __shared__ float buf[DD];
    __shared__ float r1[256], r2[256];
    const float* txt = g_text + (size_t)bn*DD;
    const float* fc = s_fc + (size_t)b*DD;
    for (int d = tid; d < DD; d += 256) buf[d] = fc[d] + txt[d];
    __syncthreads();
    float ps = 0.f;
    for (int d = tid; d < DD; d += 256) ps += buf[d];
    r1[tid] = ps; __syncthreads();
    for (int s = 128; s > 0; s >>= 1) { if (tid < s) r1[tid] += r1[tid+s]; __syncthreads(); }
    float mean = r1[0] * (1.f/DD);
    float pq = 0.f;
    for (int d = tid; d < DD; d += 256) { float x = buf[d]-mean; pq += x*x; }
    r2[tid] = pq; __syncthreads();
    for (int s = 128; s > 0; s >>= 1) { if (tid < s) r2[tid] += r2[tid+s]; __syncthreads(); }
    float rstd = rsqrtf(r2[0]*(1.f/DD) + 1e-5f);
    __half* outp = s_shift16 + (size_t)bn*DD;
    for (int d = tid; d < DD; d += 256)
        outp[d] = __float2half_rn((buf[d]-mean)*rstd*ln_g[d] + ln_b[d]);
}

// ---------------- LSTM step 0 (h=c=0): gates directly from xg ----------------
__global__ __launch_bounds__(256) void lstm_step0_kernel(float* __restrict__ out)
{
    int id = blockIdx.x*256 + threadIdx.x;   // < B*D
    int b = id / DD, jj = id - b*DD;
    uint2 raw = *reinterpret_cast<const uint2*>(&s_xg16[((size_t)b*NN)*D4 + 4*jj]);
    __half2 p0 = *(__half2*)&raw.x, p1 = *(__half2*)&raw.y;
    float gi = __low2float(p0), gg = __low2float(p1), go = __high2float(p1);
    float cn = fsig(gi) * ftanh(gg);
    s_c[id] = cn;
    float hn = fsig(go) * ftanh(cn);
    s_h16a[id] = __float2half_rn(hn);
    size_t oo = ((size_t)b*NN)*DD + jj;
    out[oo] = hn + g_text[oo];
}

// ---------------- persistent LSTM: 96 blocks, 49 steps, Whh resident in smem -------
__device__ __forceinline__ void grid_sync_96()
{
    __syncthreads();
    if (threadIdx.x == 0) {
        __threadfence();
        int gen = *(volatile int*)&g_gen;
        if (atomicAdd(&g_cnt, 1) == 95) {
            g_cnt = 0;
            __threadfence();
            *(volatile int*)&g_gen = gen + 1;
        } else {
            while (*(volatile int*)&g_gen == gen) __nanosleep(64);
        }
        __threadfence();
    }
    __syncthreads();
}

__global__ __launch_bounds__(256,1) void lstm_persistent(float* __restrict__ out)
{
    extern __shared__ __align__(16) __half S[];
    __half* Bres = S;                    // [128][PAD_B]
    __half* Ast  = S + PRS_BH;           // 3 A stages [128][ROWH]
    float*  ebuf = (float*)Ast;          // epilogue transpose (after mainloop)
    int tid = threadIdx.x;
    int bx = blockIdx.x % 24;            // N tile
    int by = blockIdx.x / 24;            // M tile

    // load resident B tile once: Whh16p rows [128*bx, +128), 768 cols
    {
        const __half* Bg = s_Whh16p + (size_t)bx*128*DD;
        for (int i = tid; i < 128*(DD/8); i += 256) {
            int r = i / (DD/8), c8 = i - r*(DD/8);
            *reinterpret_cast<uint4*>(Bres + r*PAD_B + c8*8) =
                *reinterpret_cast<const uint4*>(Bg + (size_t)r*DD + c8*8);
        }
    }
    __syncthreads();

    int lane = tid & 31, warp = tid >> 5;
    int wm = (warp >> 2) * 64, wn = (warp & 3) * 32;
    int part = lane >> 3, row8 = lane & 7;
    uint32_t offA[4], offB[2];
    #pragma unroll
    for (int mi = 0; mi < 4; mi++) {
        int r = wm + mi*16 + (part & 1)*8 + row8;
        offA[mi] = (uint32_t)(r*ROWH + (part >> 1)*8) * 2;
    }
    #pragma unroll
    for (int n2 = 0; n2 < 2; n2++) {
        int r = wn + n2*16 + (part >> 1)*8 + row8;
        offB[n2] = (uint32_t)(r*PAD_B + (part & 1)*8) * 2;
    }
    uint32_t sbA = smem_u32(Ast);
    uint32_t sbB = smem_u32(Bres);

    int g = lane >> 2, cq = lane & 3;
    int jj_l = tid & 31, rgrp = tid >> 5;

    for (int t = 1; t < NN; t++) {
        const __half* hin = (t & 1) ? s_h16a : s_h16b;
        __half* hout      = (t & 1) ? s_h16b : s_h16a;
        const __half* Ab = hin + (size_t)by*128*DD;

        auto issueA = [&](int kt, int s){
            #pragma unroll
            for (int i = 0; i < 2; i++) {
                int q = tid + i*256;
                int row = q >> 2, c = q & 3;
                uint32_t da = sbA + (uint32_t)(s*A_ST_H + row*ROWH + c*8)*2;
                const __half* ga = Ab + (size_t)row*DD + kt*32 + c*8;
                asm volatile("cp.async.cg.shared.global [%0], [%1], 16;"
                             :: "r"(da), "l"(ga) : "memory");
            }
            asm volatile("cp.async.commit_group;" ::: "memory");
        };

        float acc[4][4][4];
        #pragma unroll
        for (int i=0;i<4;i++) for (int j=0;j<4;j++) for (int r=0;r<4;r++) acc[i][j][r]=0.f;

        issueA(0, 0); issueA(1, 1);
        for (int kt = 0; kt < 24; kt++) {
            if (kt < 23) asm volatile("cp.async.wait_group 1;" ::: "memory");
            else         asm volatile("cp.async.wait_group 0;" ::: "memory");
            __syncthreads();
            if (kt + 2 < 24) issueA(kt + 2, (kt + 2) % 3);

            uint32_t abase = sbA + (uint32_t)((kt % 3)*A_ST_H)*2;
            uint32_t bcol  = (uint32_t)(kt*32)*2;
            #pragma unroll
            for (int kk = 0; kk < 2; kk++) {
                uint32_t koff = kk * 32;
                uint32_t a[4][4], bfr[4][2];
                #pragma unroll
                for (int mi = 0; mi < 4; mi++)
                    asm volatile("ldmatrix.sync.aligned.m8n8.x4.shared.b16 "
                        "{%0,%1,%2,%3}, [%4];"
                        : "=r"(a[mi][0]), "=r"(a[mi][1]), "=r"(a[mi][2]), "=r"(a[mi][3])
                        : "r"(abase + offA[mi] + koff));
                #pragma unroll
                for (int n2 = 0; n2 < 2; n2++)
                    asm volatile("ldmatrix.sync.aligned.m8n8.x4.shared.b16 "
                        "{%0,%1,%2,%3}, [%4];"
                        : "=r"(bfr[2*n2][0]), "=r"(bfr[2*n2][1]),
                          "=r"(bfr[2*n2+1][0]), "=r"(bfr[2*n2+1][1])
                        : "r"(sbB + offB[n2] + bcol + koff));
                #pragma unroll
                for (int mi = 0; mi < 4; mi++)
                    #pragma unroll
                    for (int ni = 0; ni < 4; ni++)
                        asm volatile(
                          "mma.sync.aligned.m16n8k16.row.col.f32.f16.f16.f32 "
                          "{%0,%1,%2,%3}, {%4,%5,%6,%7}, {%8,%9}, {%0,%1,%2,%3};"
                          : "+f"(acc[mi][ni][0]), "+f"(acc[mi][ni][1]),
                            "+f"(acc[mi][ni][2]), "+f"(acc[mi][ni][3])
                          : "r"(a[mi][0]), "r"(a[mi][1]), "r"(a[mi][2]), "r"(a[mi][3]),
                            "r"(bfr[ni][0]), "r"(bfr[ni][1]));
            }
            __syncthreads();
        }

        // epilogue: transpose via ebuf (reuses A-stage smem), fused LSTM gates
        #pragma unroll
        for (int hf = 0; hf < 2; hf++) {
            __syncthreads();
            if ((wm >> 6) == hf) {
                #pragma unroll
                for (int mi = 0; mi < 4; mi++)
                    #pragma unroll
                    for (int ni = 0; ni < 4; ni++) {
                        int c0 = wn + ni*8 + 2*cq;
                        int r0 = mi*16 + g;
                        *reinterpret_cast<float2*>(&ebuf[r0*128 + (c0 ^ ((r0&7)<<2))]) =
                            make_float2(acc[mi][ni][0], acc[mi][ni][1]);
                        int r1 = r0 + 8;
                        *reinterpret_cast<float2*>(&ebuf[r1*128 + (c0 ^ ((r1&7)<<2))]) =
                            make_float2(acc[mi][ni][2], acc[mi][ni][3]);
                    }
            }
            __syncthreads();
            #pragma unroll
            for (int q = 0; q < 8; q++) {
                int r = rgrp + 8*q;
                int b = by*128 + hf*64 + r;
                int jjg = bx*32 + jj_l;
                float4 acq = *reinterpret_cast<const float4*>(
                    &ebuf[r*128 + ((4*jj_l) ^ (rgrp<<2))]);
                uint2 raw = *reinterpret_cast<const uint2*>(
                    &s_xg16[((size_t)b*NN + t)*D4 + bx*128 + 4*jj_l]);
                __half2 p0 = *(__half2*)&raw.x, p1 = *(__half2*)&raw.y;
                float gi = acq.x + __low2float(p0);
                float gf = acq.y + __high2float(p0);
                float gg = acq.z + __low2float(p1);
                float go = acq.w + __high2float(p1);
                int ci = b*DD + jjg;
                float c = s_c[ci];
                float cn = fsig(gf)*c + fsig(gi)*ftanh(gg);
                s_c[ci] = cn;
                float hn = fsig(go)*ftanh(cn);
                hout[ci] = __float2half_rn(hn);
                size_t oo = ((size_t)b*NN + t)*DD + jjg;
                out[oo] = hn + g_text[oo];
            }
        }
        grid_sync_96();
    }
}

// ---------------- launch ----------------
extern "C" void kernel_launch(void* const* d_in, const int* in_sizes, int n_in,
                              void* d_out, int out_size)
{
    const float* text = (const float*)d_in[0];
    const int*   vids = (const int*)  d_in[1];
    const int*   aids = (const int*)  d_in[2];
    const float* vemb = (const float*)d_in[3];
    const float* aemb = (const float*)d_in[4];
    const float* w3   = (const float*)d_in[5];
    const float* Wih  = (const float*)d_in[6];
    const float* Whh  = (const float*)d_in[7];
    const float* bih  = (const float*)d_in[8];
    const float* bhh  = (const float*)d_in[9];
    const float* lng  = (const float*)d_in[10];
    const float* lnb  = (const float*)d_in[11];
    const float* vW   = (const float*)d_in[20];   // ca_vW [3,768,768]
    const float* vb   = (const float*)d_in[21];   // ca_vb [3,768]
    float* out = (float*)d_out;

    cudaFuncSetAttribute(lstm_persistent,
        cudaFuncAttributeMaxDynamicSharedMemorySize, PRS_SMEM);

    __half *p_vmam16, *p_shift16, *p_vWc16, *p_Wih16p, *p_xg16;
    float *p_fc, *p_vbsum, *p_bias_p;
    cudaGetSymbolAddress((void**)&p_vmam16, s_vmam16);
    cudaGetSymbolAddress((void**)&p_shift16, s_shift16);
    cudaGetSymbolAddress((void**)&p_vWc16, s_vWc16);
    cudaGetSymbolAddress((void**)&p_Wih16p, s_Wih16p);
    cudaGetSymbolAddress((void**)&p_xg16, s_xg16);
    cudaGetSymbolAddress((void**)&p_fc, s_fc);
    cudaGetSymbolAddress((void**)&p_vbsum, s_vbsum);
    cudaGetSymbolAddress((void**)&p_bias_p, s_bias_p);

    prep_kernel<<<(D4*DD + 255)/256, 256>>>(Wih, Whh, bih, bhh, vW, vb);
    egce_text<<<BB, 384>>>(text, w3);
    egce_va<<<dim3(BB, 2), 256>>>(vids, aids, vemb, aemb, w3);

    // f_cross (K=1536): fc = ([vm|am] @ [vW0|W12]^T + vbsum) * (50/3)
    gemm_f16<<<dim3(DD/128, BB/128), 256>>>(
        p_vmam16, p_vWc16, p_fc, nullptr, DD, 2*DD, p_vbsum, 50.f/3.f);

    fusion_ln_kernel<<<BB*NN, 256>>>(lng, lnb);

    // xg (fp16) = shift @ Wih_perm^T + bias_perm   [25600, 3072]
    gemm_f16<<<dim3(D4/128, (BB*NN)/128), 256>>>(
        p_shift16, p_Wih16p, nullptr, p_xg16, D4, DD, p_bias_p, 1.f);

    // LSTM: t=0 from xg; t=1..49 inside one persistent kernel
    lstm_step0_kernel<<<(BB*DD)/256, 256>>>(out);
    lstm_persistent<<<96, 256, PRS_SMEM>>>(out);
}

// round 12
// speedup vs baseline: 2.6253x; 1.3120x over previous
#include <cuda_runtime.h>
#include <cuda_fp16.h>
#include <math.h>
#include <stdint.h>

#define BB 512
#define NN 50
#define DD 768
#define D4 3072
#define FLAT (NN*DD)   // 38400

#define ROWH 40                     // halves per A smem row (80B)
#define STAGE_H (128*ROWH)

// persistent LSTM: 128 blocks, tile M128 x N96, Whh N-tile resident
#define NT 96                       // N per block
#define NBX 32                      // 3072/96
#define NBLK 128                    // 4 * 32
#define PAD_B 776                   // halves per resident-B row (1552B; 388 words = 4 mod 32)
#define PRS_BH (NT*PAD_B)           // 74496 halves = 148992 B
#define A_ST_H (128*ROWH)           // 5120 halves per A stage
#define PRS_SMEM (PRS_BH*2 + 3*A_ST_H*2)   // 148992 + 30720 = 179712 B

// ---------------- scratch (__device__ globals; no allocation allowed) ----------------
__device__ float  g_text[BB*FLAT];
__device__ __align__(16) __half s_shift16[BB*FLAT];
__device__ __align__(16) __half s_xg16[(size_t)BB*NN*D4];   // permuted gate pre-acts
__device__ __align__(16) __half s_h16a[BB*DD];
__device__ __align__(16) __half s_h16b[BB*DD];
__device__ float  s_c  [BB*DD];
__device__ __align__(16) __half s_vmam16[BB*2*DD];          // [b][vm|am]
__device__ float  s_fc [BB*DD];
__device__ __align__(16) __half s_Wih16p[(size_t)D4*DD];    // gate-interleaved rows
__device__ __align__(16) __half s_Whh16p[(size_t)D4*DD];
__device__ __align__(16) __half s_vWc16 [(size_t)DD*2*DD];  // [n][vW0|vW1+vW2]
__device__ float  s_bias_p[D4];
__device__ float  s_vbsum[DD];
__device__ int    g_cnt;
__device__ int    g_gen;

__device__ __forceinline__ float fsig(float x){
    return __fdividef(1.f, 1.f + __expf(-x));
}
__device__ __forceinline__ float ftanh(float x){
    return __fdividef(2.f, 1.f + __expf(-2.f*x)) - 1.f;
}
__device__ __forceinline__ uint32_t smem_u32(const void* p){
    uint32_t a;
    asm("{ .reg .u64 t; cvta.to.shared.u64 t, %1; cvt.u32.u64 %0, t; }"
        : "=r"(a) : "l"(p));
    return a;
}

// ---------------- prep: convert weights to fp16 (permuted), combine biases ----------
__global__ __launch_bounds__(256) void prep_kernel(
    const float* __restrict__ Wih, const float* __restrict__ Whh,
    const float* __restrict__ bih, const float* __restrict__ bhh,
    const float* __restrict__ vW,  const float* __restrict__ vb)
{
    int i = blockIdx.x*256 + threadIdx.x;
    if (i < D4*DD) {
        int p = i / DD, k = i - p*DD;
        int orig = (p & 3)*DD + (p >> 2);          // gate-interleave: p = 4*jj + gate
        s_Wih16p[i] = __float2half_rn(Wih[(size_t)orig*DD + k]);
        s_Whh16p[i] = __float2half_rn(Whh[(size_t)orig*DD + k]);
    }
    if (i < D4) {
        int orig = (i & 3)*DD + (i >> 2);
        s_bias_p[i] = bih[orig] + bhh[orig];
    }
    if (i < DD*DD) {
        int n = i / DD, k = i - n*DD;
        s_vWc16[(size_t)n*2*DD + k]      = __float2half_rn(vW[i]);
        s_vWc16[(size_t)n*2*DD + DD + k] =
            __float2half_rn(vW[DD*DD + i] + vW[2*DD*DD + i]);
    }
    if (i < DD) s_vbsum[i] = vb[i] + vb[DD+i] + vb[2*DD+i];
}

// ---------------- EGCE visual/acoustic: gated means straight from tables -----------
__global__ __launch_bounds__(256) void egce_va(
    const int* __restrict__ vids, const int* __restrict__ aids,
    const float* __restrict__ vemb, const float* __restrict__ aemb,
    const float* __restrict__ w3)
{
    int b = blockIdx.x;
    int mode = blockIdx.y;        // 0=visual(relu), 1=acoustic
    int tid = threadIdx.x;
    __shared__ int ids[NN];
    __shared__ float gap[DD], att[DD];
    if (tid < NN)
        ids[tid] = mode ? aids[b*NN+tid] : vids[b*NN+tid];
    __syncthreads();
    const float* emb = mode ? aemb : vemb;

    for (int ch = tid; ch < DD; ch += 256) {
        float s = 0.f; int base = ch*NN;
        for (int j = 0; j < NN; j++) {
            int k = base + j;
            int n = k / DD, d = k - n*DD;
            float v = emb[(size_t)ids[n]*DD + d];
            if (!mode) v = fmaxf(v, 0.f);
            s += v;
        }
        gap[ch] = s * (1.f/NN);
    }
    __syncthreads();
    float w0 = w3[0], w1 = w3[1], w2 = w3[2];
    for (int ch = tid; ch < DD; ch += 256) {
        float a = w1*gap[ch];
        if (ch > 0)    a += w0*gap[ch-1];
        if (ch < DD-1) a += w2*gap[ch+1];
        att[ch] = 1.f/(1.f+expf(-a));
    }
    __syncthreads();
    for (int d = tid; d < DD; d += 256) {
        float acc = 0.f;
        for (int n = 0; n < NN; n++) {
            float v = emb[(size_t)ids[n]*DD + d];
            if (!mode) v = fmaxf(v, 0.f);
            acc += v * att[(n*DD + d)/NN];
        }
        s_vmam16[(size_t)b*2*DD + mode*DD + d] = __float2half_rn(acc * (1.f/NN));
    }
}

// -------- fused EGCE(text) + f_cross-residual + LayerNorm -> g_text, shift16 -------
__global__ __launch_bounds__(256) void egce_ln_kernel(
    const float* __restrict__ text, const float* __restrict__ w3,
    const float* __restrict__ ln_g, const float* __restrict__ ln_b)
{
    int b = blockIdx.x, tid = threadIdx.x;
    __shared__ float gap[DD], att[DD], fcs[DD];
    const float* src = text + (size_t)b*FLAT;

    for (int ch = tid; ch < DD; ch += 256) {
        float s = 0.f; int base = ch*NN;
        #pragma unroll 5
        for (int j = 0; j < NN; j++) s += src[base+j];
        gap[ch] = s * (1.f/NN);
        fcs[ch] = s_fc[(size_t)b*DD + ch];
    }
    __syncthreads();
    float w0 = w3[0], w1 = w3[1], w2 = w3[2];
    for (int ch = tid; ch < DD; ch += 256) {
        float a = w1*gap[ch];
        if (ch > 0)    a += w0*gap[ch-1];
        if (ch < DD-1) a += w2*gap[ch+1];
        att[ch] = 1.f/(1.f+expf(-a));
    }
    __syncthreads();

    int warp = tid >> 5, lane = tid & 31;
    float* gout = g_text + (size_t)b*FLAT;
    __half* sout = s_shift16 + (size_t)b*FLAT;
    for (int n = warp; n < NN; n += 8) {
        int base = n*DD;
        float buf[24];
        float s = 0.f;
        #pragma unroll
        for (int i = 0; i < 24; i++) {
            int d = i*32 + lane;
            int k = base + d;
            float x = src[k] * att[(unsigned)k/(unsigned)NN];
            gout[k] = x;
            float v = x + fcs[d];
            buf[i] = v;
            s += v;
        }
        #pragma unroll
        for (int o = 16; o; o >>= 1) s += __shfl_xor_sync(0xFFFFFFFFu, s, o);
        float mean = s * (1.f/DD);
        float q = 0.f;
        #pragma unroll
        for (int i = 0; i < 24; i++) { float z = buf[i]-mean; q += z*z; }
        #pragma unroll
        for (int o = 16; o; o >>= 1) q += __shfl_xor_sync(0xFFFFFFFFu, q, o);
        float rstd = rsqrtf(q*(1.f/DD) + 1e-5f);
        #pragma unroll
        for (int i = 0; i < 24; i++) {
            int d = i*32 + lane;
            sout[base + d] = __float2half_rn((buf[i]-mean)*rstd*ln_g[d] + ln_b[d]);
        }
    }
}

// ================= fp16 mma mainloop (generic): 2-stage cp.async + ldmatrix ========
__device__ __forceinline__ void mainloop_f16(
    const __half* __restrict__ Ab, const __half* __restrict__ Bb, int K,
    __half* Sh, float (&acc)[4][4][4])
{
    int tid  = threadIdx.x;
    int lane = tid & 31, warp = tid >> 5;
    int wm = (warp >> 2) * 64;
    int wn = (warp & 3) * 32;
    int ntiles = K >> 5;

    int part = lane >> 3, row8 = lane & 7;
    uint32_t offA[4], offB[2];
    #pragma unroll
    for (int mi = 0; mi < 4; mi++) {
        int r = wm + mi*16 + (part & 1)*8 + row8;
        offA[mi] = (uint32_t)(r*ROWH + (part >> 1)*8) * 2;
    }
    #pragma unroll
    for (int n2 = 0; n2 < 2; n2++) {
        int r = wn + n2*16 + (part >> 1)*8 + row8;
        offB[n2] = (uint32_t)(r*ROWH + (part & 1)*8) * 2;
    }
    uint32_t sbase = smem_u32(Sh);

    auto issue = [&](int kt, int s){
        __half* As = Sh + s*2*STAGE_H;
        __half* Bs = As + STAGE_H;
        #pragma unroll
        for (int i = 0; i < 2; i++) {
            int q = tid + i*256;
            int row = q >> 2, c = q & 3;
            uint32_t da = smem_u32(As + row*ROWH + c*8);
            uint32_t db = smem_u32(Bs + row*ROWH + c*8);
            const __half* ga = Ab + (size_t)row*K + kt*32 + c*8;
            const __half* gb = Bb + (size_t)row*K + kt*32 + c*8;
            asm volatile("cp.async.cg.shared.global [%0], [%1], 16;"
                         :: "r"(da), "l"(ga) : "memory");
            asm volatile("cp.async.cg.shared.global [%0], [%1], 16;"
                         :: "r"(db), "l"(gb) : "memory");
        }
        asm volatile("cp.async.commit_group;" ::: "memory");
    };

    issue(0, 0);
    for (int kt = 0; kt < ntiles; kt++) {
        if (kt + 1 < ntiles) {
            issue(kt + 1, (kt + 1) & 1);
            asm volatile("cp.async.wait_group 1;" ::: "memory");
        } else {
            asm volatile("cp.async.wait_group 0;" ::: "memory");
        }
        __syncthreads();

        uint32_t abase = sbase + (uint32_t)(kt & 1)*2*STAGE_H*2;
        uint32_t bbase = abase + STAGE_H*2;
        #pragma unroll
        for (int kk = 0; kk < 2; kk++) {
            uint32_t koff = kk * 32;
            uint32_t a[4][4], bfr[4][2];
            #pragma unroll
            for (int mi = 0; mi < 4; mi++)
                asm volatile("ldmatrix.sync.aligned.m8n8.x4.shared.b16 "
                    "{%0,%1,%2,%3}, [%4];"
                    : "=r"(a[mi][0]), "=r"(a[mi][1]), "=r"(a[mi][2]), "=r"(a[mi][3])
                    : "r"(abase + offA[mi] + koff));
            #pragma unroll
            for (int n2 = 0; n2 < 2; n2++)
                asm volatile("ldmatrix.sync.aligned.m8n8.x4.shared.b16 "
                    "{%0,%1,%2,%3}, [%4];"
                    : "=r"(bfr[2*n2][0]), "=r"(bfr[2*n2][1]),
                      "=r"(bfr[2*n2+1][0]), "=r"(bfr[2*n2+1][1])
                    : "r"(bbase + offB[n2] + koff));
            #pragma unroll
            for (int mi = 0; mi < 4; mi++)
                #pragma unroll
                for (int ni = 0; ni < 4; ni++)
                    asm volatile(
                      "mma.sync.aligned.m16n8k16.row.col.f32.f16.f16.f32 "
                      "{%0,%1,%2,%3}, {%4,%5,%6,%7}, {%8,%9}, {%0,%1,%2,%3};"
                      : "+f"(acc[mi][ni][0]), "+f"(acc[mi][ni][1]),
                        "+f"(acc[mi][ni][2]), "+f"(acc[mi][ni][3])
                      : "r"(a[mi][0]), "r"(a[mi][1]), "r"(a[mi][2]), "r"(a[mi][3]),
                        "r"(bfr[ni][0]), "r"(bfr[ni][1]));
        }
        __syncthreads();
    }
}

// ---------------- generic GEMM: C = (A@B^T + bias)*scale; fp32 or fp16 out ---------
__global__ __launch_bounds__(256,2) void gemm_f16(
    const __half* __restrict__ A, const __half* __restrict__ Bm,
    float* __restrict__ Cf, __half* __restrict__ Ch,
    int Nn, int K, const float* __restrict__ bias, float out_scale)
{
    __shared__ __align__(16) __half Sh[4*STAGE_H];
    float acc[4][4][4];
    #pragma unroll
    for (int i=0;i<4;i++) for (int j=0;j<4;j++) for (int r=0;r<4;r++) acc[i][j][r]=0.f;

    mainloop_f16(A + (size_t)blockIdx.y*128*K, Bm + (size_t)blockIdx.x*128*K, K, Sh, acc);

    int tid = threadIdx.x;
    int warp = tid >> 5, lane = tid & 31;
    int wm = (warp >> 2) * 64, wn = (warp & 3) * 32;
    int g = lane >> 2, cq = lane & 3;
    int row0 = blockIdx.y*128 + wm;
    int col0 = blockIdx.x*128 + wn;
    #pragma unroll
    for (int mi = 0; mi < 4; mi++)
        #pragma unroll
        for (int ni = 0; ni < 4; ni++) {
            int ra = row0 + mi*16 + g;
            int rb = ra + 8;
            int n0 = col0 + ni*8 + 2*cq;
            float v0 = (acc[mi][ni][0] + bias[n0])   * out_scale;
            float v1 = (acc[mi][ni][1] + bias[n0+1]) * out_scale;
            float v2 = (acc[mi][ni][2] + bias[n0])   * out_scale;
            float v3 = (acc[mi][ni][3] + bias[n0+1]) * out_scale;
            if (Ch) {
                *(__half2*)&Ch[(size_t)ra*Nn + n0] = __floats2half2_rn(v0, v1);
                *(__half2*)&Ch[(size_t)rb*Nn + n0] = __floats2half2_rn(v2, v3);
            } else {
                Cf[(size_t)ra*Nn + n0]   = v0;
                Cf[(size_t)ra*Nn + n0+1] = v1;
                Cf[(size_t)rb*Nn + n0]   = v2;
                Cf[(size_t)rb*Nn + n0+1] = v3;
            }
        }
}

// ---------------- LSTM step 0 (h=c=0): gates directly from xg ----------------
__global__ __launch_bounds__(256) void lstm_step0_kernel(float* __restrict__ out)
{
    int id = blockIdx.x*256 + threadIdx.x;   // < B*D
    int b = id / DD, jj = id - b*DD;
    uint2 raw = *reinterpret_cast<const uint2*>(&s_xg16[((size_t)b*NN)*D4 + 4*jj]);
    __half2 p0 = *(__half2*)&raw.x, p1 = *(__half2*)&raw.y;
    float gi = __low2float(p0), gg = __low2float(p1), go = __high2float(p1);
    float cn = fsig(gi) * ftanh(gg);
    s_c[id] = cn;
    float hn = fsig(go) * ftanh(cn);
    s_h16a[id] = __float2half_rn(hn);
    size_t oo = ((size_t)b*NN)*DD + jj;
    out[oo] = hn + g_text[oo];
}

// ---------------- persistent LSTM: 128 blocks (M128xN96), Whh resident -------------
__device__ __forceinline__ void grid_sync_all()
{
    __syncthreads();
    if (threadIdx.x == 0) {
        __threadfence();
        int gen = *(volatile int*)&g_gen;
        if (atomicAdd(&g_cnt, 1) == NBLK-1) {
            g_cnt = 0;
            __threadfence();
            *(volatile int*)&g_gen = gen + 1;
        } else {
            while (*(volatile int*)&g_gen == gen) __nanosleep(64);
        }
        __threadfence();
    }
    __syncthreads();
}

__global__ __launch_bounds__(256,1) void lstm_persistent(float* __restrict__ out)
{
    extern __shared__ __align__(16) __half S[];
    __half* Bres = S;                    // [96][PAD_B]
    __half* Ast  = S + PRS_BH;           // 3 A stages [128][ROWH]
    float*  ebuf = (float*)Ast;          // epilogue transpose 64x96 (after mainloop)
    int tid = threadIdx.x;
    int bx = blockIdx.x & 31;            // N tile (96 cols)
    int by = blockIdx.x >> 5;            // M tile (128 rows)

    // load resident B tile once: Whh16p rows [96*bx, +96), 768 cols
    {
        const __half* Bg = s_Whh16p + (size_t)bx*NT*DD;
        for (int i = tid; i < NT*(DD/8); i += 256) {
            int r = i / (DD/8), c8 = i - r*(DD/8);
            *reinterpret_cast<uint4*>(Bres + r*PAD_B + c8*8) =
                *reinterpret_cast<const uint4*>(Bg + (size_t)r*DD + c8*8);
        }
    }
    __syncthreads();

    int lane = tid & 31, warp = tid >> 5;
    int wm = (warp & 3) * 32;            // 4 M-splits of 32
    int wn = (warp >> 2) * 48;           // 2 N-splits of 48
    int part = lane >> 3, row8 = lane & 7;
    uint32_t offA[2], offB[3];
    #pragma unroll
    for (int mi = 0; mi < 2; mi++) {
        int r = wm + mi*16 + (part & 1)*8 + row8;
        offA[mi] = (uint32_t)(r*ROWH + (part >> 1)*8) * 2;
    }
    #pragma unroll
    for (int n4 = 0; n4 < 3; n4++) {
        int r = wn + n4*16 + (part >> 1)*8 + row8;
        offB[n4] = (uint32_t)(r*PAD_B + (part & 1)*8) * 2;
    }
    uint32_t sbA = smem_u32(Ast);
    uint32_t sbB = smem_u32(Bres);

    int g = lane >> 2, cq = lane & 3;

    for (int t = 1; t < NN; t++) {
        const __half* hin = (t & 1) ? s_h16a : s_h16b;
        __half* hout      = (t & 1) ? s_h16b : s_h16a;
        const __half* Ab = hin + (size_t)by*128*DD;

        auto issueA = [&](int kt, int s){
            #pragma unroll
            for (int i = 0; i < 2; i++) {
                int q = tid + i*256;
                int row = q >> 2, c = q & 3;
                uint32_t da = sbA + (uint32_t)(s*A_ST_H + row*ROWH + c*8)*2;
                const __half* ga = Ab + (size_t)row*DD + kt*32 + c*8;
                asm volatile("cp.async.cg.shared.global [%0], [%1], 16;"
                             :: "r"(da), "l"(ga) : "memory");
            }
            asm volatile("cp.async.commit_group;" ::: "memory");
        };

        float acc[2][6][4];
        #pragma unroll
        for (int i=0;i<2;i++) for (int j=0;j<6;j++) for (int r=0;r<4;r++) acc[i][j][r]=0.f;

        issueA(0, 0); issueA(1, 1);
        for (int kt = 0; kt < 24; kt++) {
            if (kt < 23) asm volatile("cp.async.wait_group 1;" ::: "memory");
            else         asm volatile("cp.async.wait_group 0;" ::: "memory");
            __syncthreads();
            if (kt + 2 < 24) issueA(kt + 2, (kt + 2) % 3);

            uint32_t abase = sbA + (uint32_t)((kt % 3)*A_ST_H)*2;
            uint32_t bcol  = (uint32_t)(kt*32)*2;
            #pragma unroll
            for (int kk = 0; kk < 2; kk++) {
                uint32_t koff = kk * 32;
                uint32_t a[2][4], bfr[6][2];
                #pragma unroll
                for (int mi = 0; mi < 2; mi++)
                    asm volatile("ldmatrix.sync.aligned.m8n8.x4.shared.b16 "
                        "{%0,%1,%2,%3}, [%4];"
                        : "=r"(a[mi][0]), "=r"(a[mi][1]), "=r"(a[mi][2]), "=r"(a[mi][3])
                        : "r"(abase + offA[mi] + koff));
                #pragma unroll
                for (int n4 = 0; n4 < 3; n4++)
                    asm volatile("ldmatrix.sync.aligned.m8n8.x4.shared.b16 "
                        "{%0,%1,%2,%3}, [%4];"
                        : "=r"(bfr[2*n4][0]), "=r"(bfr[2*n4][1]),
                          "=r"(bfr[2*n4+1][0]), "=r"(bfr[2*n4+1][1])
                        : "r"(sbB + offB[n4] + bcol + koff));
                #pragma unroll
                for (int mi = 0; mi < 2; mi++)
                    #pragma unroll
                    for (int ni = 0; ni < 6; ni++)
                        asm volatile(
                          "mma.sync.aligned.m16n8k16.row.col.f32.f16.f16.f32 "
                          "{%0,%1,%2,%3}, {%4,%5,%6,%7}, {%8,%9}, {%0,%1,%2,%3};"
                          : "+f"(acc[mi][ni][0]), "+f"(acc[mi][ni][1]),
                            "+f"(acc[mi][ni][2]), "+f"(acc[mi][ni][3])
                          : "r"(a[mi][0]), "r"(a[mi][1]), "r"(a[mi][2]), "r"(a[mi][3]),
                            "r"(bfr[ni][0]), "r"(bfr[ni][1]));
            }
            __syncthreads();
        }

        // epilogue: per 64-row half, transpose via ebuf then fused LSTM gates
        #pragma unroll
        for (int hf = 0; hf < 2; hf++) {
            __syncthreads();
            if (((warp & 3) >> 1) == hf) {
                int rbase = ((warp & 3) & 1)*32;
                #pragma unroll
                for (int mi = 0; mi < 2; mi++)
                    #pragma unroll
                    for (int ni = 0; ni < 6; ni++) {
                        int c0 = wn + ni*8 + 2*cq;
                        int r0 = rbase + mi*16 + g;
                        *reinterpret_cast<float2*>(&ebuf[r0*NT + (c0 ^ ((r0&7)<<2))]) =
                            make_float2(acc[mi][ni][0], acc[mi][ni][1]);
                        int r1 = r0 + 8;
                        *reinterpret_cast<float2*>(&ebuf[r1*NT + (c0 ^ ((r1&7)<<2))]) =
                            make_float2(acc[mi][ni][2], acc[mi][ni][3]);
                    }
            }
            __syncthreads();
            #pragma unroll
            for (int q = 0; q < 6; q++) {
                int idx = tid + q*256;          // < 1536
                int r = idx / 24, j = idx - r*24;
                int b = by*128 + hf*64 + r;
                int jjg = bx*24 + j;
                float4 acq = *reinterpret_cast<const float4*>(
                    &ebuf[r*NT + ((4*j) ^ ((r&7)<<2))]);
                uint2 raw = *reinterpret_cast<const uint2*>(
                    &s_xg16[((size_t)b*NN + t)*D4 + bx*NT + 4*j]);
                __half2 p0 = *(__half2*)&raw.x, p1 = *(__half2*)&raw.y;
                float gi = acq.x + __low2float(p0);
                float gf = acq.y + __high2float(p0);
                float gg = acq.z + __low2float(p1);
                float go = acq.w + __high2float(p1);
                int ci = b*DD + jjg;
                float c = s_c[ci];
                float cn = fsig(gf)*c + fsig(gi)*ftanh(gg);
                s_c[ci] = cn;
                float hn = fsig(go)*ftanh(cn);
                hout[ci] = __float2half_rn(hn);
                size_t oo = ((size_t)b*NN + t)*DD + jjg;
                out[oo] = hn + g_text[oo];
            }
        }
        grid_sync_all();
    }
}

// ---------------- launch ----------------
extern "C" void kernel_launch(void* const* d_in, const int* in_sizes, int n_in,
                              void* d_out, int out_size)
{
    const float* text = (const float*)d_in[0];
    const int*   vids = (const int*)  d_in[1];
    const int*   aids = (const int*)  d_in[2];
    const float* vemb = (const float*)d_in[3];
    const float* aemb = (const float*)d_in[4];
    const float* w3   = (const float*)d_in[5];
    const float* Wih  = (const float*)d_in[6];
    const float* Whh  = (const float*)d_in[7];
    const float* bih  = (const float*)d_in[8];
    const float* bhh  = (const float*)d_in[9];
    const float* lng  = (const float*)d_in[10];
    const float* lnb  = (const float*)d_in[11];
    const float* vW   = (const float*)d_in[20];   // ca_vW [3,768,768]
    const float* vb   = (const float*)d_in[21];   // ca_vb [3,768]
    float* out = (float*)d_out;

    cudaFuncSetAttribute(lstm_persistent,
        cudaFuncAttributeMaxDynamicSharedMemorySize, PRS_SMEM);

    __half *p_vmam16, *p_shift16, *p_vWc16, *p_Wih16p, *p_xg16;
    float *p_fc, *p_vbsum, *p_bias_p;
    cudaGetSymbolAddress((void**)&p_vmam16, s_vmam16);
    cudaGetSymbolAddress((void**)&p_shift16, s_shift16);
    cudaGetSymbolAddress((void**)&p_vWc16, s_vWc16);
    cudaGetSymbolAddress((void**)&p_Wih16p, s_Wih16p);
    cudaGetSymbolAddress((void**)&p_xg16, s_xg16);
    cudaGetSymbolAddress((void**)&p_fc, s_fc);
    cudaGetSymbolAddress((void**)&p_vbsum, s_vbsum);
    cudaGetSymbolAddress((void**)&p_bias_p, s_bias_p);

    prep_kernel<<<(D4*DD + 255)/256, 256>>>(Wih, Whh, bih, bhh, vW, vb);
    egce_va<<<dim3(BB, 2), 256>>>(vids, aids, vemb, aemb, w3);

    // f_cross (K=1536): fc = ([vm|am] @ [vW0|W12]^T + vbsum) * (50/3)
    gemm_f16<<<dim3(DD/128, BB/128), 256>>>(
        p_vmam16, p_vWc16, p_fc, nullptr, DD, 2*DD, p_vbsum, 50.f/3.f);

    // fused egce(text) + fusion residual + LN
    egce_ln_kernel<<<BB, 256>>>(text, w3, lng, lnb);

    // xg (fp16) = shift @ Wih_perm^T + bias_perm   [25600, 3072]
    gemm_f16<<<dim3(D4/128, (BB*NN)/128), 256>>>(
        p_shift16, p_Wih16p, nullptr, p_xg16, D4, DD, p_bias_p, 1.f);

    // LSTM: t=0 from xg; t=1..49 inside one persistent kernel (128 blocks)
    lstm_step0_kernel<<<(BB*DD)/256, 256>>>(out);
    lstm_persistent<<<NBLK, 256, PRS_SMEM>>>(out);
}